// round 1
// baseline (speedup 1.0000x reference)
#include <cuda_runtime.h>
#include <math.h>

#define NN 20000
#define NE 160000
#define FDIM 256
#define HID 128
#define HEADS 4
#define DH 128
#define FSD 512
#define EPSB 1e-5f

// ------------------- device scratch (no allocations allowed) -------------------
__device__ float g_h256[NN * FDIM];
__device__ float g_agg[NN * FDIM];
__device__ float g_hidden[NN * HID];
__device__ float g_x[NN * HID];
__device__ float g_x2[NN * HID];
__device__ float g_fsf[NN * FSD];
__device__ float g_fsb[NN * FSD];
__device__ float g_acc[NN * FSD];
__device__ float g_elf[NN * HEADS], g_erf[NN * HEADS];
__device__ float g_elb[NN * HEADS], g_erb[NN * HEADS];
__device__ float g_mf[NN * HEADS], g_sf[NN * HEADS];
__device__ float g_mb[NN * HEADS], g_sb[NN * HEADS];
__device__ int   g_cin[NN], g_cout[NN];
__device__ int   g_iin[NN + 1], g_iout[NN + 1];
__device__ int   g_ein[NE], g_eout[NE];
__device__ float g_bsum[HID], g_bsq[HID];

// ------------------- small utility kernels -------------------
__global__ void k_zeroi(int* p, int n) {
    int i = blockIdx.x * blockDim.x + threadIdx.x;
    if (i < n) p[i] = 0;
}
__global__ void k_zerof(float* p, int n) {
    int i = blockIdx.x * blockDim.x + threadIdx.x;
    if (i < n) p[i] = 0.f;
}

// ------------------- CSR build -------------------
__global__ void k_hist(const int* __restrict__ src, const int* __restrict__ dst,
                       int* __restrict__ cin, int* __restrict__ cout) {
    int e = blockIdx.x * blockDim.x + threadIdx.x;
    if (e < NE) {
        atomicAdd(&cin[dst[e]], 1);
        atomicAdd(&cout[src[e]], 1);
    }
}

// single-block exclusive scan over NN counts -> indptr[NN+1]
__global__ void k_scan(const int* __restrict__ cnt, int* __restrict__ indptr) {
    __shared__ int ssum[1024];
    const int CH = 20;  // 1024*20 = 20480 >= NN
    int tid = threadIdx.x;
    int base = tid * CH;
    int s = 0;
    for (int i = 0; i < CH; i++)
        if (base + i < NN) s += cnt[base + i];
    ssum[tid] = s;
    __syncthreads();
    for (int off = 1; off < 1024; off <<= 1) {
        int v = (tid >= off) ? ssum[tid - off] : 0;
        __syncthreads();
        ssum[tid] += v;
        __syncthreads();
    }
    int run = (tid == 0) ? 0 : ssum[tid - 1];
    for (int i = 0; i < CH; i++) {
        if (base + i < NN) {
            indptr[base + i] = run;
            run += cnt[base + i];
        }
    }
    if (tid == 1023) indptr[NN] = ssum[1023];
}

__global__ void k_scatter(const int* __restrict__ key, const int* __restrict__ indptr,
                          int* __restrict__ cur, int* __restrict__ eidx) {
    int e = blockIdx.x * blockDim.x + threadIdx.x;
    if (e < NE) {
        int k = key[e];
        int p = indptr[k] + atomicAdd(&cur[k], 1);
        eidx[p] = e;
    }
}

// ------------------- weighted GCN aggregation -------------------
// agg[n, :] = sum over edges with key==n of feat[other[e], :] * ew[e]
__global__ void k_wgcn(const float* __restrict__ feat, const float* __restrict__ ew,
                       const int* __restrict__ indptr, const int* __restrict__ eidx,
                       const int* __restrict__ other, float* __restrict__ agg) {
    int n = blockIdx.x;
    int tid = threadIdx.x;  // 256 = FDIM
    int beg = indptr[n], end = indptr[n + 1];
    float acc = 0.f;
    for (int j = beg; j < end; j++) {
        int e = eidx[j];
        float w = ew[e];
        int u = other[e];
        acc += w * feat[(size_t)u * FDIM + tid];
    }
    agg[(size_t)n * FDIM + tid] = acc;
}

// ------------------- tiled fp32 GEMM: C = [C +] act(A@B + bias) -------------------
#define BM 128
#define BN 64
#define BK 16
__global__ void k_gemm(const float* __restrict__ A, const float* __restrict__ B,
                       const float* __restrict__ bias, float* __restrict__ C,
                       int M, int N, int K, int doAcc, int doRelu) {
    __shared__ float As[BK][BM];
    __shared__ float Bs[BK][BN];
    int bm = blockIdx.y * BM;
    int bn = blockIdx.x * BN;
    int tid = threadIdx.x;  // 256
    int tx = tid & 15;      // 4 cols each
    int ty = tid >> 4;      // 8 rows each
    float acc[8][4];
#pragma unroll
    for (int i = 0; i < 8; i++)
#pragma unroll
        for (int j = 0; j < 4; j++) acc[i][j] = 0.f;

    int arow = tid >> 1;          // 0..127
    int acol = (tid & 1) * 8;     // 0 or 8
    int brow = tid >> 4;          // 0..15
    int bcol = (tid & 15) * 4;
    int agrow = bm + arow;
    if (agrow >= M) agrow = M - 1;  // clamp; results for these rows are discarded

    for (int k0 = 0; k0 < K; k0 += BK) {
        float4 a0 = *(const float4*)&A[(size_t)agrow * K + k0 + acol];
        float4 a1 = *(const float4*)&A[(size_t)agrow * K + k0 + acol + 4];
        As[acol + 0][arow] = a0.x; As[acol + 1][arow] = a0.y;
        As[acol + 2][arow] = a0.z; As[acol + 3][arow] = a0.w;
        As[acol + 4][arow] = a1.x; As[acol + 5][arow] = a1.y;
        As[acol + 6][arow] = a1.z; As[acol + 7][arow] = a1.w;
        float4 bv = *(const float4*)&B[(size_t)(k0 + brow) * N + bn + bcol];
        *(float4*)&Bs[brow][bcol] = bv;
        __syncthreads();
#pragma unroll
        for (int kk = 0; kk < BK; kk++) {
            float av[8], bvv[4];
#pragma unroll
            for (int i = 0; i < 8; i++) av[i] = As[kk][ty * 8 + i];
#pragma unroll
            for (int j = 0; j < 4; j++) bvv[j] = Bs[kk][tx * 4 + j];
#pragma unroll
            for (int i = 0; i < 8; i++)
#pragma unroll
                for (int j = 0; j < 4; j++) acc[i][j] = fmaf(av[i], bvv[j], acc[i][j]);
        }
        __syncthreads();
    }
#pragma unroll
    for (int i = 0; i < 8; i++) {
        int m = bm + ty * 8 + i;
        if (m >= M) break;
#pragma unroll
        for (int j = 0; j < 4; j++) {
            int n = bn + tx * 4 + j;
            float v = acc[i][j];
            if (bias) v += bias[n];
            if (doRelu) v = v > 0.f ? v : 0.f;
            size_t idx = (size_t)m * N + n;
            if (doAcc) v += C[idx];
            C[idx] = v;
        }
    }
}

// ------------------- GAT attention pieces -------------------
// el[n,h] = dot(fs[n,h,:], al[h,:]) ; er same with ar. One warp per node.
__global__ void k_elr(const float* __restrict__ fs, const float* __restrict__ al,
                      const float* __restrict__ ar, float* __restrict__ el,
                      float* __restrict__ er) {
    int w = (blockIdx.x * blockDim.x + threadIdx.x) >> 5;
    int lane = threadIdx.x & 31;
    if (w >= NN) return;
    const float* f = fs + (size_t)w * FSD;
#pragma unroll
    for (int h = 0; h < HEADS; h++) {
        float sl = 0.f, sr = 0.f;
#pragma unroll
        for (int d = lane; d < DH; d += 32) {
            float v = f[h * DH + d];
            sl += v * al[h * DH + d];
            sr += v * ar[h * DH + d];
        }
#pragma unroll
        for (int off = 16; off > 0; off >>= 1) {
            sl += __shfl_xor_sync(0xffffffffu, sl, off);
            sr += __shfl_xor_sync(0xffffffffu, sr, off);
        }
        if (lane == 0) { el[w * HEADS + h] = sl; er[w * HEADS + h] = sr; }
    }
}

// per-node softmax stats: m[n,h] = max_e lrelu(el[other]+er[n]); s = sum exp(e-m)
__global__ void k_stats(const int* __restrict__ indptr, const int* __restrict__ eidx,
                        const int* __restrict__ other, const float* __restrict__ el,
                        const float* __restrict__ er, float* __restrict__ mo,
                        float* __restrict__ so) {
    int w = (blockIdx.x * blockDim.x + threadIdx.x) >> 5;
    int lane = threadIdx.x & 31;
    if (w >= NN) return;
    int beg = indptr[w], end = indptr[w + 1];
    float ern[HEADS];
#pragma unroll
    for (int h = 0; h < HEADS; h++) ern[h] = er[w * HEADS + h];
    float mh[HEADS];
#pragma unroll
    for (int h = 0; h < HEADS; h++) mh[h] = -1e30f;
    for (int j = beg + lane; j < end; j += 32) {
        int u = other[eidx[j]];
#pragma unroll
        for (int h = 0; h < HEADS; h++) {
            float e = el[u * HEADS + h] + ern[h];
            e = e > 0.f ? e : 0.2f * e;
            mh[h] = fmaxf(mh[h], e);
        }
    }
#pragma unroll
    for (int off = 16; off > 0; off >>= 1)
#pragma unroll
        for (int h = 0; h < HEADS; h++)
            mh[h] = fmaxf(mh[h], __shfl_xor_sync(0xffffffffu, mh[h], off));
    float sh[HEADS] = {0.f, 0.f, 0.f, 0.f};
    for (int j = beg + lane; j < end; j += 32) {
        int u = other[eidx[j]];
#pragma unroll
        for (int h = 0; h < HEADS; h++) {
            float e = el[u * HEADS + h] + ern[h];
            e = e > 0.f ? e : 0.2f * e;
            sh[h] += expf(e - mh[h]);
        }
    }
#pragma unroll
    for (int off = 16; off > 0; off >>= 1)
#pragma unroll
        for (int h = 0; h < HEADS; h++)
            sh[h] += __shfl_xor_sync(0xffffffffu, sh[h], off);
    if (lane == 0)
#pragma unroll
        for (int h = 0; h < HEADS; h++) {
            mo[w * HEADS + h] = mh[h];
            so[w * HEADS + h] = sh[h];
        }
}

// acc[n, h*128+d] (+)= sum_e  exp(e - m)/s * fs[other, h*128+d]
__global__ void k_gat_agg(const float* __restrict__ fs, const float* __restrict__ el,
                          const float* __restrict__ er, const float* __restrict__ mArr,
                          const float* __restrict__ sArr, const int* __restrict__ indptr,
                          const int* __restrict__ eidx, const int* __restrict__ other,
                          float* __restrict__ acc, int doAcc) {
    int n = blockIdx.x;
    int tid = threadIdx.x;  // 128 = DH
    int beg = indptr[n], end = indptr[n + 1];
    float* arow = acc + (size_t)n * FSD;
    if (beg == end) {
        if (!doAcc) {
#pragma unroll
            for (int h = 0; h < HEADS; h++) arow[h * DH + tid] = 0.f;
        }
        return;
    }
    __shared__ float wsh[32][HEADS];
    __shared__ int ush[32];
    float ern[HEADS], mm[HEADS], sinv[HEADS];
#pragma unroll
    for (int h = 0; h < HEADS; h++) {
        ern[h] = er[n * HEADS + h];
        mm[h] = mArr[n * HEADS + h];
        sinv[h] = 1.f / sArr[n * HEADS + h];
    }
    float rf[HEADS] = {0.f, 0.f, 0.f, 0.f};
    for (int c = beg; c < end; c += 32) {
        int ne = end - c;
        if (ne > 32) ne = 32;
        if (tid < ne * HEADS) {
            int j = tid >> 2, h = tid & 3;
            int e = eidx[c + j];
            int u = other[e];
            if (h == 0) ush[j] = u;
            float ev = el[u * HEADS + h] + ern[h];
            ev = ev > 0.f ? ev : 0.2f * ev;
            wsh[j][h] = expf(ev - mm[h]) * sinv[h];
        }
        __syncthreads();
        for (int j = 0; j < ne; j++) {
            int u = ush[j];
            const float* frow = fs + (size_t)u * FSD;
#pragma unroll
            for (int h = 0; h < HEADS; h++)
                rf[h] += wsh[j][h] * frow[h * DH + tid];
        }
        __syncthreads();
    }
#pragma unroll
    for (int h = 0; h < HEADS; h++) {
        float v = rf[h];
        if (doAcc) v += arow[h * DH + tid];
        arow[h * DH + tid] = v;
    }
}

// ------------------- elementwise glue -------------------
__global__ void k_idcombine(const float* __restrict__ feat, float* __restrict__ h256) {
    int i = blockIdx.x * blockDim.x + threadIdx.x;
    if (i < NN * FDIM) {
        float f = feat[i];
        float h = h256[i];
        h256[i] = f + h * (1.f / (1.f + expf(-f)));
    }
}

__global__ void k_mean(const float* __restrict__ acc, float* __restrict__ xout) {
    int i = blockIdx.x * blockDim.x + threadIdx.x;
    if (i < NN * HID) {
        int n = i >> 7, d = i & 127;
        const float* a = acc + (size_t)n * FSD;
        xout[i] = 0.25f * (a[d] + a[DH + d] + a[2 * DH + d] + a[3 * DH + d]);
    }
}

__global__ void k_add(float* __restrict__ hidden, const float* __restrict__ x) {
    int i = blockIdx.x * blockDim.x + threadIdx.x;
    if (i < NN * HID) hidden[i] += x[i];
}

// ------------------- batch norm -------------------
__global__ void k_bnstats(const float* __restrict__ h, float* __restrict__ bsum,
                          float* __restrict__ bsq) {
    __shared__ float s1[256], s2[256];
    int tid = threadIdx.x;
    int c = tid & 127;
    int half = tid >> 7;
    int rbeg = blockIdx.x * 128;
    int rend = rbeg + 128;
    if (rend > NN) rend = NN;
    float sm = 0.f, sq = 0.f;
    for (int r = rbeg + half; r < rend; r += 2) {
        float v = h[(size_t)r * HID + c];
        sm += v;
        sq += v * v;
    }
    s1[tid] = sm;
    s2[tid] = sq;
    __syncthreads();
    if (tid < 128) {
        atomicAdd(&bsum[c], s1[tid] + s1[tid + 128]);
        atomicAdd(&bsq[c], s2[tid] + s2[tid + 128]);
    }
}

__global__ void k_bnapply(const float* __restrict__ h, const float* __restrict__ bsum,
                          const float* __restrict__ bsq, const float* __restrict__ gamma,
                          const float* __restrict__ beta, float* __restrict__ out) {
    int i = blockIdx.x * blockDim.x + threadIdx.x;
    if (i < NN * HID) {
        int c = i & 127;
        float mu = bsum[c] * (1.f / NN);
        float var = bsq[c] * (1.f / NN) - mu * mu;
        out[i] = gamma[c] * (h[i] - mu) * rsqrtf(var + EPSB) + beta[c];
    }
}

// ------------------- launch -------------------
extern "C" void kernel_launch(void* const* d_in, const int* in_sizes, int n_in,
                              void* d_out, int out_size) {
    const float* feature  = (const float*)d_in[0];
    const float* ew_f     = (const float*)d_in[1];
    const float* ew_b     = (const float*)d_in[2];
    const float* W_id     = (const float*)d_in[3];
    const float* b_id     = (const float*)d_in[4];
    const float* W_gcnf   = (const float*)d_in[5];
    const float* b_gcnf   = (const float*)d_in[6];
    const float* W_gcnb   = (const float*)d_in[7];
    const float* b_gcnb   = (const float*)d_in[8];
    const float* W1       = (const float*)d_in[9];
    const float* b1       = (const float*)d_in[10];
    const float* gat_W    = (const float*)d_in[11];
    const float* gat_al   = (const float*)d_in[12];
    const float* gat_ar   = (const float*)d_in[13];
    const float* bn_gamma = (const float*)d_in[14];
    const float* bn_beta  = (const float*)d_in[15];
    const int*   src      = (const int*)d_in[16];
    const int*   dst      = (const int*)d_in[17];
    float* out = (float*)d_out;

    float *p_h256, *p_agg, *p_hidden, *p_x, *p_x2, *p_fsf, *p_fsb, *p_acc;
    float *p_elf, *p_erf, *p_elb, *p_erb, *p_mf, *p_sf, *p_mb, *p_sb, *p_bsum, *p_bsq;
    int *p_cin, *p_cout, *p_iin, *p_iout, *p_ein, *p_eout;
    cudaGetSymbolAddress((void**)&p_h256, g_h256);
    cudaGetSymbolAddress((void**)&p_agg, g_agg);
    cudaGetSymbolAddress((void**)&p_hidden, g_hidden);
    cudaGetSymbolAddress((void**)&p_x, g_x);
    cudaGetSymbolAddress((void**)&p_x2, g_x2);
    cudaGetSymbolAddress((void**)&p_fsf, g_fsf);
    cudaGetSymbolAddress((void**)&p_fsb, g_fsb);
    cudaGetSymbolAddress((void**)&p_acc, g_acc);
    cudaGetSymbolAddress((void**)&p_elf, g_elf);
    cudaGetSymbolAddress((void**)&p_erf, g_erf);
    cudaGetSymbolAddress((void**)&p_elb, g_elb);
    cudaGetSymbolAddress((void**)&p_erb, g_erb);
    cudaGetSymbolAddress((void**)&p_mf, g_mf);
    cudaGetSymbolAddress((void**)&p_sf, g_sf);
    cudaGetSymbolAddress((void**)&p_mb, g_mb);
    cudaGetSymbolAddress((void**)&p_sb, g_sb);
    cudaGetSymbolAddress((void**)&p_bsum, g_bsum);
    cudaGetSymbolAddress((void**)&p_bsq, g_bsq);
    cudaGetSymbolAddress((void**)&p_cin, g_cin);
    cudaGetSymbolAddress((void**)&p_cout, g_cout);
    cudaGetSymbolAddress((void**)&p_iin, g_iin);
    cudaGetSymbolAddress((void**)&p_iout, g_iout);
    cudaGetSymbolAddress((void**)&p_ein, g_ein);
    cudaGetSymbolAddress((void**)&p_eout, g_eout);

    const int EB = (NE + 255) / 256;
    const int NB = (NN + 255) / 256;
    const int NHB = (NN * HID + 255) / 256;
    const int NFB = (NN * FDIM + 255) / 256;
    const int WARPB = (NN * 32 + 127) / 128;  // one warp/node kernels

    // --- CSR build (both directions) ---
    k_zeroi<<<NB, 256>>>(p_cin, NN);
    k_zeroi<<<NB, 256>>>(p_cout, NN);
    k_hist<<<EB, 256>>>(src, dst, p_cin, p_cout);
    k_scan<<<1, 1024>>>(p_cin, p_iin);
    k_scan<<<1, 1024>>>(p_cout, p_iout);
    k_zeroi<<<NB, 256>>>(p_cin, NN);
    k_zeroi<<<NB, 256>>>(p_cout, NN);
    k_scatter<<<EB, 256>>>(dst, p_iin, p_cin, p_ein);
    k_scatter<<<EB, 256>>>(src, p_iout, p_cout, p_eout);

    // --- Identity layer: lin + fwd WGCN + bwd WGCN ---
    {
        dim3 g(FDIM / BN, (NN + BM - 1) / BM);
        k_gemm<<<g, 256>>>(feature, W_id, b_id, p_h256, NN, FDIM, FDIM, 0, 0);
        k_wgcn<<<NN, 256>>>(feature, ew_f, p_iin, p_ein, src, p_agg);
        k_gemm<<<g, 256>>>(p_agg, W_gcnf, b_gcnf, p_h256, NN, FDIM, FDIM, 1, 1);
        k_wgcn<<<NN, 256>>>(feature, ew_b, p_iout, p_eout, dst, p_agg);
        k_gemm<<<g, 256>>>(p_agg, W_gcnb, b_gcnb, p_h256, NN, FDIM, FDIM, 1, 1);
        k_idcombine<<<NFB, 256>>>(feature, p_h256);
        dim3 g1(HID / BN, (NN + BM - 1) / BM);
        k_gemm<<<g1, 256>>>(p_h256, W1, b1, p_hidden, NN, HID, FDIM, 0, 0);
    }

    // --- 2 layers x 2 GAT blocks ---
    for (int l = 0; l < 2; l++) {
        const float* xin = p_hidden;
        float* xouts[2] = {p_x, p_x2};
        for (int blk = 0; blk < 2; blk++) {
            int base = (l * 2 + blk) * 2;
            const float* Wf = gat_W + (size_t)(base + 0) * HID * FSD;
            const float* Wb = gat_W + (size_t)(base + 1) * HID * FSD;
            const float* alf = gat_al + (size_t)(base + 0) * HEADS * DH;
            const float* arf = gat_ar + (size_t)(base + 0) * HEADS * DH;
            const float* alb = gat_al + (size_t)(base + 1) * HEADS * DH;
            const float* arb = gat_ar + (size_t)(base + 1) * HEADS * DH;

            dim3 g(FSD / BN, (NN + BM - 1) / BM);
            k_gemm<<<g, 256>>>(xin, Wf, (const float*)0, p_fsf, NN, FSD, HID, 0, 0);
            k_gemm<<<g, 256>>>(xin, Wb, (const float*)0, p_fsb, NN, FSD, HID, 0, 0);
            k_elr<<<WARPB, 128>>>(p_fsf, alf, arf, p_elf, p_erf);
            k_elr<<<WARPB, 128>>>(p_fsb, alb, arb, p_elb, p_erb);
            // forward gat: group by dst (CSR_in), neighbor = src
            k_stats<<<WARPB, 128>>>(p_iin, p_ein, src, p_elf, p_erf, p_mf, p_sf);
            // backward gat: group by src (CSR_out), neighbor = dst
            k_stats<<<WARPB, 128>>>(p_iout, p_eout, dst, p_elb, p_erb, p_mb, p_sb);
            k_gat_agg<<<NN, 128>>>(p_fsf, p_elf, p_erf, p_mf, p_sf, p_iin, p_ein, src, p_acc, 0);
            k_gat_agg<<<NN, 128>>>(p_fsb, p_elb, p_erb, p_mb, p_sb, p_iout, p_eout, dst, p_acc, 1);
            float* xo = xouts[blk];
            k_mean<<<NHB, 256>>>(p_acc, xo);
            xin = xo;
        }
        k_add<<<NHB, 256>>>(p_hidden, p_x2);  // hidden = x + hidden
    }

    // --- BatchNorm (training-mode batch stats) ---
    k_zerof<<<1, 128>>>(p_bsum, HID);
    k_zerof<<<1, 128>>>(p_bsq, HID);
    k_bnstats<<<(NN + 127) / 128, 256>>>(p_hidden, p_bsum, p_bsq);
    k_bnapply<<<NHB, 256>>>(p_hidden, p_bsum, p_bsq, bn_gamma, bn_beta, out);
}

// round 2
// speedup vs baseline: 1.0036x; 1.0036x over previous
#include <cuda_runtime.h>
#include <math.h>

#define NN 20000
#define NE 160000
#define FDIM 256
#define HID 128
#define HEADS 4
#define DH 128
#define FSD 512
#define EPSB 1e-5f

// ------------------- device scratch (no allocations allowed) -------------------
__device__ float g_h256[NN * FDIM];
__device__ float g_agg[NN * FDIM];
__device__ float g_hidden[NN * HID];
__device__ float g_x[NN * HID];
__device__ float g_x2[NN * HID];
__device__ float g_fsf[NN * FSD];
__device__ float g_fsb[NN * FSD];
__device__ float g_acc[NN * FSD];
__device__ float g_elf[NN * HEADS], g_erf[NN * HEADS];
__device__ float g_elb[NN * HEADS], g_erb[NN * HEADS];
__device__ float g_mf[NN * HEADS], g_sf[NN * HEADS];
__device__ float g_mb[NN * HEADS], g_sb[NN * HEADS];
__device__ int   g_cin[NN], g_cout[NN];
__device__ int   g_iin[NN + 1], g_iout[NN + 1];
__device__ int   g_ein[NE], g_eout[NE];
__device__ float g_bsum[HID], g_bsq[HID];

// ------------------- small utility kernels -------------------
__global__ void k_zeroi(int* p, int n) {
    int i = blockIdx.x * blockDim.x + threadIdx.x;
    if (i < n) p[i] = 0;
}
__global__ void k_zerof(float* p, int n) {
    int i = blockIdx.x * blockDim.x + threadIdx.x;
    if (i < n) p[i] = 0.f;
}

// ------------------- CSR build -------------------
__global__ void k_hist(const int* __restrict__ src, const int* __restrict__ dst,
                       int* __restrict__ cin, int* __restrict__ cout) {
    int e = blockIdx.x * blockDim.x + threadIdx.x;
    if (e < NE) {
        atomicAdd(&cin[dst[e]], 1);
        atomicAdd(&cout[src[e]], 1);
    }
}

// single-block exclusive scan over NN counts -> indptr[NN+1]
__global__ void k_scan(const int* __restrict__ cnt, int* __restrict__ indptr) {
    __shared__ int ssum[1024];
    const int CH = 20;  // 1024*20 = 20480 >= NN
    int tid = threadIdx.x;
    int base = tid * CH;
    int s = 0;
    for (int i = 0; i < CH; i++)
        if (base + i < NN) s += cnt[base + i];
    ssum[tid] = s;
    __syncthreads();
    for (int off = 1; off < 1024; off <<= 1) {
        int v = (tid >= off) ? ssum[tid - off] : 0;
        __syncthreads();
        ssum[tid] += v;
        __syncthreads();
    }
    int run = (tid == 0) ? 0 : ssum[tid - 1];
    for (int i = 0; i < CH; i++) {
        if (base + i < NN) {
            indptr[base + i] = run;
            run += cnt[base + i];
        }
    }
    if (tid == 1023) indptr[NN] = ssum[1023];
}

__global__ void k_scatter(const int* __restrict__ key, const int* __restrict__ indptr,
                          int* __restrict__ cur, int* __restrict__ eidx) {
    int e = blockIdx.x * blockDim.x + threadIdx.x;
    if (e < NE) {
        int k = key[e];
        int p = indptr[k] + atomicAdd(&cur[k], 1);
        eidx[p] = e;
    }
}

// ------------------- weighted GCN aggregation -------------------
__global__ void k_wgcn(const float* __restrict__ feat, const float* __restrict__ ew,
                       const int* __restrict__ indptr, const int* __restrict__ eidx,
                       const int* __restrict__ other, float* __restrict__ agg) {
    int n = blockIdx.x;
    int tid = threadIdx.x;  // 256 = FDIM
    int beg = indptr[n], end = indptr[n + 1];
    float acc = 0.f;
    for (int j = beg; j < end; j++) {
        int e = eidx[j];
        float w = ew[e];
        int u = other[e];
        acc += w * feat[(size_t)u * FDIM + tid];
    }
    agg[(size_t)n * FDIM + tid] = acc;
}

// ------------------- tiled fp32 GEMM: C = [C +] act(A@B + bias) -------------------
// 128x128 block tile, 8x8 per-thread microtile, BK=16, register prefetch.
#define BM 128
#define BN 128
#define BK 16
__global__ __launch_bounds__(256, 2)
void k_gemm(const float* __restrict__ A, const float* __restrict__ B,
            const float* __restrict__ bias, float* __restrict__ C,
            int M, int N, int K, int doAcc, int doRelu) {
    __shared__ float As[BK][BM + 4];
    __shared__ float Bs[BK][BN];
    int bm = blockIdx.y * BM;
    int bn = blockIdx.x * BN;
    int tid = threadIdx.x;      // 256
    int tm = tid >> 4;          // 0..15 -> rows tm*8..+8
    int tn = tid & 15;          // 0..15 -> cols tn*8..+8

    // A load mapping: each thread 8 k-consecutive floats of one row
    int arow = tid >> 1;              // 0..127
    int acol = (tid & 1) * 8;         // 0 or 8
    int agrow = bm + arow;
    if (agrow >= M) agrow = M - 1;    // clamp; clamped rows never stored
    const float* Aptr = A + (size_t)agrow * K + acol;
    // B load mapping: each thread 8 n-consecutive floats of one k-row
    int brow = tid >> 4;              // 0..15
    int bcol = (tid & 15) * 8;        // 0..120
    const float* Bptr = B + (size_t)brow * N + bn + bcol;

    float acc[8][8];
#pragma unroll
    for (int i = 0; i < 8; i++)
#pragma unroll
        for (int j = 0; j < 8; j++) acc[i][j] = 0.f;

    float4 pa0 = *(const float4*)(Aptr + 0);
    float4 pa1 = *(const float4*)(Aptr + 4);
    float4 pb0 = *(const float4*)(Bptr + 0);
    float4 pb1 = *(const float4*)(Bptr + 4);

    for (int k0 = 0; k0 < K; k0 += BK) {
        As[acol + 0][arow] = pa0.x; As[acol + 1][arow] = pa0.y;
        As[acol + 2][arow] = pa0.z; As[acol + 3][arow] = pa0.w;
        As[acol + 4][arow] = pa1.x; As[acol + 5][arow] = pa1.y;
        As[acol + 6][arow] = pa1.z; As[acol + 7][arow] = pa1.w;
        *(float4*)&Bs[brow][bcol] = pb0;
        *(float4*)&Bs[brow][bcol + 4] = pb1;
        __syncthreads();
        if (k0 + BK < K) {
            pa0 = *(const float4*)(Aptr + k0 + BK);
            pa1 = *(const float4*)(Aptr + k0 + BK + 4);
            pb0 = *(const float4*)(Bptr + (size_t)(k0 + BK) * N);
            pb1 = *(const float4*)(Bptr + (size_t)(k0 + BK) * N + 4);
        }
#pragma unroll
        for (int kk = 0; kk < BK; kk++) {
            float4 av0 = *(const float4*)&As[kk][tm * 8];
            float4 av1 = *(const float4*)&As[kk][tm * 8 + 4];
            float4 bv0 = *(const float4*)&Bs[kk][tn * 8];
            float4 bv1 = *(const float4*)&Bs[kk][tn * 8 + 4];
            float av[8] = {av0.x, av0.y, av0.z, av0.w, av1.x, av1.y, av1.z, av1.w};
            float bv[8] = {bv0.x, bv0.y, bv0.z, bv0.w, bv1.x, bv1.y, bv1.z, bv1.w};
#pragma unroll
            for (int i = 0; i < 8; i++)
#pragma unroll
                for (int j = 0; j < 8; j++)
                    acc[i][j] = fmaf(av[i], bv[j], acc[i][j]);
        }
        __syncthreads();
    }

    float bb[8];
    if (bias) {
        float4 b0 = *(const float4*)&bias[bn + tn * 8];
        float4 b1 = *(const float4*)&bias[bn + tn * 8 + 4];
        bb[0] = b0.x; bb[1] = b0.y; bb[2] = b0.z; bb[3] = b0.w;
        bb[4] = b1.x; bb[5] = b1.y; bb[6] = b1.z; bb[7] = b1.w;
    } else {
#pragma unroll
        for (int j = 0; j < 8; j++) bb[j] = 0.f;
    }
#pragma unroll
    for (int i = 0; i < 8; i++) {
        int m = bm + tm * 8 + i;
        if (m >= M) break;
        float* crow = C + (size_t)m * N + bn + tn * 8;
        float v[8];
#pragma unroll
        for (int j = 0; j < 8; j++) {
            float t = acc[i][j] + bb[j];
            if (doRelu) t = t > 0.f ? t : 0.f;
            v[j] = t;
        }
        if (doAcc) {
            float4 c0 = *(const float4*)crow;
            float4 c1 = *(const float4*)(crow + 4);
            v[0] += c0.x; v[1] += c0.y; v[2] += c0.z; v[3] += c0.w;
            v[4] += c1.x; v[5] += c1.y; v[6] += c1.z; v[7] += c1.w;
        }
        *(float4*)crow = make_float4(v[0], v[1], v[2], v[3]);
        *(float4*)(crow + 4) = make_float4(v[4], v[5], v[6], v[7]);
    }
}

// ------------------- GAT attention pieces -------------------
__global__ void k_elr(const float* __restrict__ fs, const float* __restrict__ al,
                      const float* __restrict__ ar, float* __restrict__ el,
                      float* __restrict__ er) {
    int w = (blockIdx.x * blockDim.x + threadIdx.x) >> 5;
    int lane = threadIdx.x & 31;
    if (w >= NN) return;
    const float* f = fs + (size_t)w * FSD;
#pragma unroll
    for (int h = 0; h < HEADS; h++) {
        float sl = 0.f, sr = 0.f;
#pragma unroll
        for (int d = lane; d < DH; d += 32) {
            float v = f[h * DH + d];
            sl += v * al[h * DH + d];
            sr += v * ar[h * DH + d];
        }
#pragma unroll
        for (int off = 16; off > 0; off >>= 1) {
            sl += __shfl_xor_sync(0xffffffffu, sl, off);
            sr += __shfl_xor_sync(0xffffffffu, sr, off);
        }
        if (lane == 0) { el[w * HEADS + h] = sl; er[w * HEADS + h] = sr; }
    }
}

__global__ void k_stats(const int* __restrict__ indptr, const int* __restrict__ eidx,
                        const int* __restrict__ other, const float* __restrict__ el,
                        const float* __restrict__ er, float* __restrict__ mo,
                        float* __restrict__ so) {
    int w = (blockIdx.x * blockDim.x + threadIdx.x) >> 5;
    int lane = threadIdx.x & 31;
    if (w >= NN) return;
    int beg = indptr[w], end = indptr[w + 1];
    float ern[HEADS];
#pragma unroll
    for (int h = 0; h < HEADS; h++) ern[h] = er[w * HEADS + h];
    float mh[HEADS];
#pragma unroll
    for (int h = 0; h < HEADS; h++) mh[h] = -1e30f;
    for (int j = beg + lane; j < end; j += 32) {
        int u = other[eidx[j]];
#pragma unroll
        for (int h = 0; h < HEADS; h++) {
            float e = el[u * HEADS + h] + ern[h];
            e = e > 0.f ? e : 0.2f * e;
            mh[h] = fmaxf(mh[h], e);
        }
    }
#pragma unroll
    for (int off = 16; off > 0; off >>= 1)
#pragma unroll
        for (int h = 0; h < HEADS; h++)
            mh[h] = fmaxf(mh[h], __shfl_xor_sync(0xffffffffu, mh[h], off));
    float sh[HEADS] = {0.f, 0.f, 0.f, 0.f};
    for (int j = beg + lane; j < end; j += 32) {
        int u = other[eidx[j]];
#pragma unroll
        for (int h = 0; h < HEADS; h++) {
            float e = el[u * HEADS + h] + ern[h];
            e = e > 0.f ? e : 0.2f * e;
            sh[h] += expf(e - mh[h]);
        }
    }
#pragma unroll
    for (int off = 16; off > 0; off >>= 1)
#pragma unroll
        for (int h = 0; h < HEADS; h++)
            sh[h] += __shfl_xor_sync(0xffffffffu, sh[h], off);
    if (lane == 0)
#pragma unroll
        for (int h = 0; h < HEADS; h++) {
            mo[w * HEADS + h] = mh[h];
            so[w * HEADS + h] = sh[h];
        }
}

__global__ void k_gat_agg(const float* __restrict__ fs, const float* __restrict__ el,
                          const float* __restrict__ er, const float* __restrict__ mArr,
                          const float* __restrict__ sArr, const int* __restrict__ indptr,
                          const int* __restrict__ eidx, const int* __restrict__ other,
                          float* __restrict__ acc, int doAcc) {
    int n = blockIdx.x;
    int tid = threadIdx.x;  // 128 = DH
    int beg = indptr[n], end = indptr[n + 1];
    float* arow = acc + (size_t)n * FSD;
    if (beg == end) {
        if (!doAcc) {
#pragma unroll
            for (int h = 0; h < HEADS; h++) arow[h * DH + tid] = 0.f;
        }
        return;
    }
    __shared__ float wsh[32][HEADS];
    __shared__ int ush[32];
    float ern[HEADS], mm[HEADS], sinv[HEADS];
#pragma unroll
    for (int h = 0; h < HEADS; h++) {
        ern[h] = er[n * HEADS + h];
        mm[h] = mArr[n * HEADS + h];
        sinv[h] = 1.f / sArr[n * HEADS + h];
    }
    float rf[HEADS] = {0.f, 0.f, 0.f, 0.f};
    for (int c = beg; c < end; c += 32) {
        int ne = end - c;
        if (ne > 32) ne = 32;
        if (tid < ne * HEADS) {
            int j = tid >> 2, h = tid & 3;
            int e = eidx[c + j];
            int u = other[e];
            if (h == 0) ush[j] = u;
            float ev = el[u * HEADS + h] + ern[h];
            ev = ev > 0.f ? ev : 0.2f * ev;
            wsh[j][h] = expf(ev - mm[h]) * sinv[h];
        }
        __syncthreads();
        for (int j = 0; j < ne; j++) {
            int u = ush[j];
            const float* frow = fs + (size_t)u * FSD;
#pragma unroll
            for (int h = 0; h < HEADS; h++)
                rf[h] += wsh[j][h] * frow[h * DH + tid];
        }
        __syncthreads();
    }
#pragma unroll
    for (int h = 0; h < HEADS; h++) {
        float v = rf[h];
        if (doAcc) v += arow[h * DH + tid];
        arow[h * DH + tid] = v;
    }
}

// ------------------- elementwise glue -------------------
__global__ void k_idcombine(const float* __restrict__ feat, float* __restrict__ h256) {
    int i = blockIdx.x * blockDim.x + threadIdx.x;
    if (i < NN * FDIM) {
        float f = feat[i];
        float h = h256[i];
        h256[i] = f + h * (1.f / (1.f + expf(-f)));
    }
}

// mean over heads; optionally add into residual target instead of plain write
__global__ void k_mean(const float* __restrict__ acc, float* __restrict__ xout, int doAdd) {
    int i = blockIdx.x * blockDim.x + threadIdx.x;
    if (i < NN * HID) {
        int n = i >> 7, d = i & 127;
        const float* a = acc + (size_t)n * FSD;
        float v = 0.25f * (a[d] + a[DH + d] + a[2 * DH + d] + a[3 * DH + d]);
        if (doAdd) xout[i] += v;
        else xout[i] = v;
    }
}

// ------------------- batch norm -------------------
__global__ void k_bnstats(const float* __restrict__ h, float* __restrict__ bsum,
                          float* __restrict__ bsq) {
    __shared__ float s1[256], s2[256];
    int tid = threadIdx.x;
    int c = tid & 127;
    int half = tid >> 7;
    int rbeg = blockIdx.x * 128;
    int rend = rbeg + 128;
    if (rend > NN) rend = NN;
    float sm = 0.f, sq = 0.f;
    for (int r = rbeg + half; r < rend; r += 2) {
        float v = h[(size_t)r * HID + c];
        sm += v;
        sq += v * v;
    }
    s1[tid] = sm;
    s2[tid] = sq;
    __syncthreads();
    if (tid < 128) {
        atomicAdd(&bsum[c], s1[tid] + s1[tid + 128]);
        atomicAdd(&bsq[c], s2[tid] + s2[tid + 128]);
    }
}

__global__ void k_bnapply(const float* __restrict__ h, const float* __restrict__ bsum,
                          const float* __restrict__ bsq, const float* __restrict__ gamma,
                          const float* __restrict__ beta, float* __restrict__ out) {
    int i = blockIdx.x * blockDim.x + threadIdx.x;
    if (i < NN * HID) {
        int c = i & 127;
        float mu = bsum[c] * (1.f / NN);
        float var = bsq[c] * (1.f / NN) - mu * mu;
        out[i] = gamma[c] * (h[i] - mu) * rsqrtf(var + EPSB) + beta[c];
    }
}

// ------------------- launch -------------------
extern "C" void kernel_launch(void* const* d_in, const int* in_sizes, int n_in,
                              void* d_out, int out_size) {
    const float* feature  = (const float*)d_in[0];
    const float* ew_f     = (const float*)d_in[1];
    const float* ew_b     = (const float*)d_in[2];
    const float* W_id     = (const float*)d_in[3];
    const float* b_id     = (const float*)d_in[4];
    const float* W_gcnf   = (const float*)d_in[5];
    const float* b_gcnf   = (const float*)d_in[6];
    const float* W_gcnb   = (const float*)d_in[7];
    const float* b_gcnb   = (const float*)d_in[8];
    const float* W1       = (const float*)d_in[9];
    const float* b1       = (const float*)d_in[10];
    const float* gat_W    = (const float*)d_in[11];
    const float* gat_al   = (const float*)d_in[12];
    const float* gat_ar   = (const float*)d_in[13];
    const float* bn_gamma = (const float*)d_in[14];
    const float* bn_beta  = (const float*)d_in[15];
    const int*   src      = (const int*)d_in[16];
    const int*   dst      = (const int*)d_in[17];
    float* out = (float*)d_out;

    float *p_h256, *p_agg, *p_hidden, *p_x, *p_x2, *p_fsf, *p_fsb, *p_acc;
    float *p_elf, *p_erf, *p_elb, *p_erb, *p_mf, *p_sf, *p_mb, *p_sb, *p_bsum, *p_bsq;
    int *p_cin, *p_cout, *p_iin, *p_iout, *p_ein, *p_eout;
    cudaGetSymbolAddress((void**)&p_h256, g_h256);
    cudaGetSymbolAddress((void**)&p_agg, g_agg);
    cudaGetSymbolAddress((void**)&p_hidden, g_hidden);
    cudaGetSymbolAddress((void**)&p_x, g_x);
    cudaGetSymbolAddress((void**)&p_x2, g_x2);
    cudaGetSymbolAddress((void**)&p_fsf, g_fsf);
    cudaGetSymbolAddress((void**)&p_fsb, g_fsb);
    cudaGetSymbolAddress((void**)&p_acc, g_acc);
    cudaGetSymbolAddress((void**)&p_elf, g_elf);
    cudaGetSymbolAddress((void**)&p_erf, g_erf);
    cudaGetSymbolAddress((void**)&p_elb, g_elb);
    cudaGetSymbolAddress((void**)&p_erb, g_erb);
    cudaGetSymbolAddress((void**)&p_mf, g_mf);
    cudaGetSymbolAddress((void**)&p_sf, g_sf);
    cudaGetSymbolAddress((void**)&p_mb, g_mb);
    cudaGetSymbolAddress((void**)&p_sb, g_sb);
    cudaGetSymbolAddress((void**)&p_bsum, g_bsum);
    cudaGetSymbolAddress((void**)&p_bsq, g_bsq);
    cudaGetSymbolAddress((void**)&p_cin, g_cin);
    cudaGetSymbolAddress((void**)&p_cout, g_cout);
    cudaGetSymbolAddress((void**)&p_iin, g_iin);
    cudaGetSymbolAddress((void**)&p_iout, g_iout);
    cudaGetSymbolAddress((void**)&p_ein, g_ein);
    cudaGetSymbolAddress((void**)&p_eout, g_eout);

    const int EB = (NE + 255) / 256;
    const int NB = (NN + 255) / 256;
    const int NHB = (NN * HID + 255) / 256;
    const int NFB = (NN * FDIM + 255) / 256;
    const int WARPB = (NN * 32 + 127) / 128;  // one warp/node kernels
    const int MB = (NN + BM - 1) / BM;        // 157

    // --- CSR build (both directions) ---
    k_zeroi<<<NB, 256>>>(p_cin, NN);
    k_zeroi<<<NB, 256>>>(p_cout, NN);
    k_hist<<<EB, 256>>>(src, dst, p_cin, p_cout);
    k_scan<<<1, 1024>>>(p_cin, p_iin);
    k_scan<<<1, 1024>>>(p_cout, p_iout);
    k_zeroi<<<NB, 256>>>(p_cin, NN);
    k_zeroi<<<NB, 256>>>(p_cout, NN);
    k_scatter<<<EB, 256>>>(dst, p_iin, p_cin, p_ein);
    k_scatter<<<EB, 256>>>(src, p_iout, p_cout, p_eout);

    // --- Identity layer: lin + fwd WGCN + bwd WGCN ---
    {
        dim3 g(FDIM / BN, MB);
        k_gemm<<<g, 256>>>(feature, W_id, b_id, p_h256, NN, FDIM, FDIM, 0, 0);
        k_wgcn<<<NN, 256>>>(feature, ew_f, p_iin, p_ein, src, p_agg);
        k_gemm<<<g, 256>>>(p_agg, W_gcnf, b_gcnf, p_h256, NN, FDIM, FDIM, 1, 1);
        k_wgcn<<<NN, 256>>>(feature, ew_b, p_iout, p_eout, dst, p_agg);
        k_gemm<<<g, 256>>>(p_agg, W_gcnb, b_gcnb, p_h256, NN, FDIM, FDIM, 1, 1);
        k_idcombine<<<NFB, 256>>>(feature, p_h256);
        dim3 g1(HID / BN, MB);
        k_gemm<<<g1, 256>>>(p_h256, W1, b1, p_hidden, NN, HID, FDIM, 0, 0);
    }

    // --- 2 layers x 2 GAT blocks ---
    for (int l = 0; l < 2; l++) {
        const float* xin = p_hidden;
        for (int blk = 0; blk < 2; blk++) {
            int base = (l * 2 + blk) * 2;
            const float* Wf = gat_W + (size_t)(base + 0) * HID * FSD;
            const float* Wb = gat_W + (size_t)(base + 1) * HID * FSD;
            const float* alf = gat_al + (size_t)(base + 0) * HEADS * DH;
            const float* arf = gat_ar + (size_t)(base + 0) * HEADS * DH;
            const float* alb = gat_al + (size_t)(base + 1) * HEADS * DH;
            const float* arb = gat_ar + (size_t)(base + 1) * HEADS * DH;

            dim3 g(FSD / BN, MB);
            k_gemm<<<g, 256>>>(xin, Wf, (const float*)0, p_fsf, NN, FSD, HID, 0, 0);
            k_gemm<<<g, 256>>>(xin, Wb, (const float*)0, p_fsb, NN, FSD, HID, 0, 0);
            k_elr<<<WARPB, 128>>>(p_fsf, alf, arf, p_elf, p_erf);
            k_elr<<<WARPB, 128>>>(p_fsb, alb, arb, p_elb, p_erb);
            // forward gat: group by dst (CSR_in), neighbor = src
            k_stats<<<WARPB, 128>>>(p_iin, p_ein, src, p_elf, p_erf, p_mf, p_sf);
            // backward gat: group by src (CSR_out), neighbor = dst
            k_stats<<<WARPB, 128>>>(p_iout, p_eout, dst, p_elb, p_erb, p_mb, p_sb);
            k_gat_agg<<<NN, 128>>>(p_fsf, p_elf, p_erf, p_mf, p_sf, p_iin, p_ein, src, p_acc, 0);
            k_gat_agg<<<NN, 128>>>(p_fsb, p_elb, p_erb, p_mb, p_sb, p_iout, p_eout, dst, p_acc, 1);
            if (blk == 0) {
                k_mean<<<NHB, 256>>>(p_acc, p_x, 0);
                xin = p_x;
            } else {
                // hidden = mean(acc) + hidden  (residual, fused)
                k_mean<<<NHB, 256>>>(p_acc, p_hidden, 1);
            }
        }
    }

    // --- BatchNorm (training-mode batch stats) ---
    k_zerof<<<1, 128>>>(p_bsum, HID);
    k_zerof<<<1, 128>>>(p_bsq, HID);
    k_bnstats<<<(NN + 127) / 128, 256>>>(p_hidden, p_bsum, p_bsq);
    k_bnapply<<<NHB, 256>>>(p_hidden, p_bsum, p_bsq, bn_gamma, bn_beta, out);
}

// round 4
// speedup vs baseline: 1.4282x; 1.4231x over previous
#include <cuda_runtime.h>
#include <math.h>
#include <stdint.h>

#define NN 20000
#define NE 160000
#define FDIM 256
#define HID 128
#define HEADS 4
#define DH 128
#define FSD 512
#define EPSB 1e-5f

// ------------------- device scratch (no allocations allowed) -------------------
__device__ float g_h256[NN * FDIM];
__device__ float g_agg[NN * FDIM];
__device__ float g_hidden[NN * HID];
__device__ float g_x[NN * HID];
__device__ float g_fsf[NN * FSD];
__device__ float g_fsb[NN * FSD];
__device__ float g_acc[NN * FSD];
__device__ float g_elf[NN * HEADS], g_erf[NN * HEADS];
__device__ float g_elb[NN * HEADS], g_erb[NN * HEADS];
__device__ float g_mf[NN * HEADS], g_sf[NN * HEADS];
__device__ float g_mb[NN * HEADS], g_sb[NN * HEADS];
__device__ int   g_cin[NN], g_cout[NN];
__device__ int   g_iin[NN + 1], g_iout[NN + 1];
__device__ int   g_ein[NE], g_eout[NE];
__device__ float g_bsum[HID], g_bsq[HID];

// ------------------- small utility kernels -------------------
__global__ void k_zeroi(int* p, int n) {
    int i = blockIdx.x * blockDim.x + threadIdx.x;
    if (i < n) p[i] = 0;
}
__global__ void k_zerof(float* p, int n) {
    int i = blockIdx.x * blockDim.x + threadIdx.x;
    if (i < n) p[i] = 0.f;
}

// ------------------- CSR build -------------------
__global__ void k_hist(const int* __restrict__ src, const int* __restrict__ dst,
                       int* __restrict__ cin, int* __restrict__ cout) {
    int e = blockIdx.x * blockDim.x + threadIdx.x;
    if (e < NE) {
        atomicAdd(&cin[dst[e]], 1);
        atomicAdd(&cout[src[e]], 1);
    }
}

__global__ void k_scan(const int* __restrict__ cnt, int* __restrict__ indptr) {
    __shared__ int ssum[1024];
    const int CH = 20;
    int tid = threadIdx.x;
    int base = tid * CH;
    int s = 0;
    for (int i = 0; i < CH; i++)
        if (base + i < NN) s += cnt[base + i];
    ssum[tid] = s;
    __syncthreads();
    for (int off = 1; off < 1024; off <<= 1) {
        int v = (tid >= off) ? ssum[tid - off] : 0;
        __syncthreads();
        ssum[tid] += v;
        __syncthreads();
    }
    int run = (tid == 0) ? 0 : ssum[tid - 1];
    for (int i = 0; i < CH; i++) {
        if (base + i < NN) {
            indptr[base + i] = run;
            run += cnt[base + i];
        }
    }
    if (tid == 1023) indptr[NN] = ssum[1023];
}

__global__ void k_scatter(const int* __restrict__ key, const int* __restrict__ indptr,
                          int* __restrict__ cur, int* __restrict__ eidx) {
    int e = blockIdx.x * blockDim.x + threadIdx.x;
    if (e < NE) {
        int k = key[e];
        int p = indptr[k] + atomicAdd(&cur[k], 1);
        eidx[p] = e;
    }
}

// ------------------- weighted GCN aggregation -------------------
__global__ void k_wgcn(const float* __restrict__ feat, const float* __restrict__ ew,
                       const int* __restrict__ indptr, const int* __restrict__ eidx,
                       const int* __restrict__ other, float* __restrict__ agg) {
    int n = blockIdx.x;
    int tid = threadIdx.x;  // 256 = FDIM
    int beg = indptr[n], end = indptr[n + 1];
    float acc = 0.f;
    for (int j = beg; j < end; j++) {
        int e = eidx[j];
        float w = ew[e];
        int u = other[e];
        acc += w * feat[(size_t)u * FDIM + tid];
    }
    agg[(size_t)n * FDIM + tid] = acc;
}

// ------------------- TF32 tensor-core GEMM: C = [C +] act(A@B + bias) -------------------
// BM=128, BN=64, BK=32. 8 warps as 4(m) x 2(n); warp tile 32x32 via m16n8k8.
#define BM 128
#define BN 64
#define BK 32
#define APAD 4
#define BPAD 8

__device__ __forceinline__ uint32_t f2tf32(float x) {
    uint32_t y;
    asm("cvt.rna.tf32.f32 %0, %1;" : "=r"(y) : "f"(x));
    return y;
}

__device__ __forceinline__ void mma_tf32(float* c, uint32_t a0, uint32_t a1,
                                         uint32_t a2, uint32_t a3,
                                         uint32_t b0, uint32_t b1) {
    asm volatile(
        "mma.sync.aligned.m16n8k8.row.col.f32.tf32.tf32.f32 "
        "{%0,%1,%2,%3}, {%4,%5,%6,%7}, {%8,%9}, {%0,%1,%2,%3};"
        : "+f"(c[0]), "+f"(c[1]), "+f"(c[2]), "+f"(c[3])
        : "r"(a0), "r"(a1), "r"(a2), "r"(a3), "r"(b0), "r"(b1));
}

__global__ __launch_bounds__(256, 2)
void k_gemm(const float* __restrict__ A, const float* __restrict__ B,
            const float* __restrict__ bias, float* __restrict__ C,
            int M, int N, int K, int doAcc, int doRelu) {
    __shared__ uint32_t As[BM][BK + APAD];   // [m][k] tf32 bits
    __shared__ uint32_t Bs[BK][BN + BPAD];   // [k][n] tf32 bits
    int bm = blockIdx.y * BM;
    int bn = blockIdx.x * BN;
    int tid = threadIdx.x;
    int wid = tid >> 5, lane = tid & 31;
    int wm = (wid >> 1) * 32;   // 0,32,64,96
    int wn = (wid & 1) * 32;    // 0,32
    int grp = lane >> 2, tig = lane & 3;

    float c[2][4][4];
#pragma unroll
    for (int im = 0; im < 2; im++)
#pragma unroll
        for (int jn = 0; jn < 4; jn++)
#pragma unroll
            for (int r = 0; r < 4; r++) c[im][jn][r] = 0.f;

    // A gmem mapping: float4 idx = tid + 256*i (i<4): row = idx>>3, c4 = (idx&7)*4
    int ar[4], ac[4];
#pragma unroll
    for (int i = 0; i < 4; i++) {
        int idx = tid + 256 * i;
        ar[i] = idx >> 3;
        ac[i] = (idx & 7) * 4;
    }
    // B gmem mapping: float4 idx = tid + 256*i (i<2): row = idx>>4, c4 = (idx&15)*4
    int br[2], bc[2];
#pragma unroll
    for (int i = 0; i < 2; i++) {
        int idx = tid + 256 * i;
        br[i] = idx >> 4;
        bc[i] = (idx & 15) * 4;
    }

    float4 pa[4], pb[2];
#pragma unroll
    for (int i = 0; i < 4; i++) {
        int m = bm + ar[i]; if (m >= M) m = M - 1;
        pa[i] = *(const float4*)&A[(size_t)m * K + ac[i]];
    }
#pragma unroll
    for (int i = 0; i < 2; i++)
        pb[i] = *(const float4*)&B[(size_t)br[i] * N + bn + bc[i]];

    for (int k0 = 0; k0 < K; k0 += BK) {
#pragma unroll
        for (int i = 0; i < 4; i++) {
            As[ar[i]][ac[i] + 0] = f2tf32(pa[i].x);
            As[ar[i]][ac[i] + 1] = f2tf32(pa[i].y);
            As[ar[i]][ac[i] + 2] = f2tf32(pa[i].z);
            As[ar[i]][ac[i] + 3] = f2tf32(pa[i].w);
        }
#pragma unroll
        for (int i = 0; i < 2; i++) {
            Bs[br[i]][bc[i] + 0] = f2tf32(pb[i].x);
            Bs[br[i]][bc[i] + 1] = f2tf32(pb[i].y);
            Bs[br[i]][bc[i] + 2] = f2tf32(pb[i].z);
            Bs[br[i]][bc[i] + 3] = f2tf32(pb[i].w);
        }
        __syncthreads();
        if (k0 + BK < K) {
#pragma unroll
            for (int i = 0; i < 4; i++) {
                int m = bm + ar[i]; if (m >= M) m = M - 1;
                pa[i] = *(const float4*)&A[(size_t)m * K + k0 + BK + ac[i]];
            }
#pragma unroll
            for (int i = 0; i < 2; i++)
                pb[i] = *(const float4*)&B[(size_t)(k0 + BK + br[i]) * N + bn + bc[i]];
        }
#pragma unroll
        for (int ks = 0; ks < BK / 8; ks++) {
            int kk = ks * 8;
            uint32_t af[2][4], bf[4][2];
#pragma unroll
            for (int im = 0; im < 2; im++) {
                int mb_ = wm + im * 16;
                af[im][0] = As[mb_ + grp][kk + tig];
                af[im][1] = As[mb_ + 8 + grp][kk + tig];
                af[im][2] = As[mb_ + grp][kk + tig + 4];
                af[im][3] = As[mb_ + 8 + grp][kk + tig + 4];
            }
#pragma unroll
            for (int jn = 0; jn < 4; jn++) {
                int nb_ = wn + jn * 8;
                bf[jn][0] = Bs[kk + tig][nb_ + grp];
                bf[jn][1] = Bs[kk + tig + 4][nb_ + grp];
            }
#pragma unroll
            for (int im = 0; im < 2; im++)
#pragma unroll
                for (int jn = 0; jn < 4; jn++)
                    mma_tf32(c[im][jn], af[im][0], af[im][1], af[im][2], af[im][3],
                             bf[jn][0], bf[jn][1]);
        }
        __syncthreads();
    }

    // epilogue: c[im][jn][r] -> row = bm+wm+im*16+grp+(r>=2?8:0), col = bn+wn+jn*8+2*tig+(r&1)
#pragma unroll
    for (int im = 0; im < 2; im++) {
#pragma unroll
        for (int half = 0; half < 2; half++) {
            int m = bm + wm + im * 16 + grp + half * 8;
            if (m >= M) continue;
#pragma unroll
            for (int jn = 0; jn < 4; jn++) {
                int col = bn + wn + jn * 8 + 2 * tig;
                float v0 = c[im][jn][half * 2 + 0];
                float v1 = c[im][jn][half * 2 + 1];
                if (bias) {
                    float2 bb = *(const float2*)&bias[col];
                    v0 += bb.x; v1 += bb.y;
                }
                if (doRelu) {
                    v0 = v0 > 0.f ? v0 : 0.f;
                    v1 = v1 > 0.f ? v1 : 0.f;
                }
                float* cp = C + (size_t)m * N + col;
                if (doAcc) {
                    float2 cv = *(const float2*)cp;
                    v0 += cv.x; v1 += cv.y;
                }
                *(float2*)cp = make_float2(v0, v1);
            }
        }
    }
}

// ------------------- GAT attention pieces -------------------
__global__ void k_elr(const float* __restrict__ fs, const float* __restrict__ al,
                      const float* __restrict__ ar, float* __restrict__ el,
                      float* __restrict__ er) {
    int w = (blockIdx.x * blockDim.x + threadIdx.x) >> 5;
    int lane = threadIdx.x & 31;
    if (w >= NN) return;
    const float* f = fs + (size_t)w * FSD;
#pragma unroll
    for (int h = 0; h < HEADS; h++) {
        float sl = 0.f, sr = 0.f;
#pragma unroll
        for (int d = lane; d < DH; d += 32) {
            float v = f[h * DH + d];
            sl += v * al[h * DH + d];
            sr += v * ar[h * DH + d];
        }
#pragma unroll
        for (int off = 16; off > 0; off >>= 1) {
            sl += __shfl_xor_sync(0xffffffffu, sl, off);
            sr += __shfl_xor_sync(0xffffffffu, sr, off);
        }
        if (lane == 0) { el[w * HEADS + h] = sl; er[w * HEADS + h] = sr; }
    }
}

__global__ void k_stats(const int* __restrict__ indptr, const int* __restrict__ eidx,
                        const int* __restrict__ other, const float* __restrict__ el,
                        const float* __restrict__ er, float* __restrict__ mo,
                        float* __restrict__ so) {
    int w = (blockIdx.x * blockDim.x + threadIdx.x) >> 5;
    int lane = threadIdx.x & 31;
    if (w >= NN) return;
    int beg = indptr[w], end = indptr[w + 1];
    float ern[HEADS];
#pragma unroll
    for (int h = 0; h < HEADS; h++) ern[h] = er[w * HEADS + h];
    float mh[HEADS];
#pragma unroll
    for (int h = 0; h < HEADS; h++) mh[h] = -1e30f;
    for (int j = beg + lane; j < end; j += 32) {
        int u = other[eidx[j]];
#pragma unroll
        for (int h = 0; h < HEADS; h++) {
            float e = el[u * HEADS + h] + ern[h];
            e = e > 0.f ? e : 0.2f * e;
            mh[h] = fmaxf(mh[h], e);
        }
    }
#pragma unroll
    for (int off = 16; off > 0; off >>= 1)
#pragma unroll
        for (int h = 0; h < HEADS; h++)
            mh[h] = fmaxf(mh[h], __shfl_xor_sync(0xffffffffu, mh[h], off));
    float sh[HEADS] = {0.f, 0.f, 0.f, 0.f};
    for (int j = beg + lane; j < end; j += 32) {
        int u = other[eidx[j]];
#pragma unroll
        for (int h = 0; h < HEADS; h++) {
            float e = el[u * HEADS + h] + ern[h];
            e = e > 0.f ? e : 0.2f * e;
            sh[h] += expf(e - mh[h]);
        }
    }
#pragma unroll
    for (int off = 16; off > 0; off >>= 1)
#pragma unroll
        for (int h = 0; h < HEADS; h++)
            sh[h] += __shfl_xor_sync(0xffffffffu, sh[h], off);
    if (lane == 0)
#pragma unroll
        for (int h = 0; h < HEADS; h++) {
            mo[w * HEADS + h] = mh[h];
            so[w * HEADS + h] = sh[h];
        }
}

__global__ void k_gat_agg(const float* __restrict__ fs, const float* __restrict__ el,
                          const float* __restrict__ er, const float* __restrict__ mArr,
                          const float* __restrict__ sArr, const int* __restrict__ indptr,
                          const int* __restrict__ eidx, const int* __restrict__ other,
                          float* __restrict__ acc, int doAcc) {
    int n = blockIdx.x;
    int tid = threadIdx.x;  // 128 = DH
    int beg = indptr[n], end = indptr[n + 1];
    float* arow = acc + (size_t)n * FSD;
    if (beg == end) {
        if (!doAcc) {
#pragma unroll
            for (int h = 0; h < HEADS; h++) arow[h * DH + tid] = 0.f;
        }
        return;
    }
    __shared__ float wsh[32][HEADS];
    __shared__ int ush[32];
    float ern[HEADS], mm[HEADS], sinv[HEADS];
#pragma unroll
    for (int h = 0; h < HEADS; h++) {
        ern[h] = er[n * HEADS + h];
        mm[h] = mArr[n * HEADS + h];
        sinv[h] = 1.f / sArr[n * HEADS + h];
    }
    float rf[HEADS] = {0.f, 0.f, 0.f, 0.f};
    for (int c = beg; c < end; c += 32) {
        int ne = end - c;
        if (ne > 32) ne = 32;
        if (tid < ne * HEADS) {
            int j = tid >> 2, h = tid & 3;
            int e = eidx[c + j];
            int u = other[e];
            if (h == 0) ush[j] = u;
            float ev = el[u * HEADS + h] + ern[h];
            ev = ev > 0.f ? ev : 0.2f * ev;
            wsh[j][h] = expf(ev - mm[h]) * sinv[h];
        }
        __syncthreads();
        for (int j = 0; j < ne; j++) {
            int u = ush[j];
            const float* frow = fs + (size_t)u * FSD;
#pragma unroll
            for (int h = 0; h < HEADS; h++)
                rf[h] += wsh[j][h] * frow[h * DH + tid];
        }
        __syncthreads();
    }
#pragma unroll
    for (int h = 0; h < HEADS; h++) {
        float v = rf[h];
        if (doAcc) v += arow[h * DH + tid];
        arow[h * DH + tid] = v;
    }
}

// ------------------- elementwise glue -------------------
__global__ void k_idcombine(const float* __restrict__ feat, float* __restrict__ h256) {
    int i = blockIdx.x * blockDim.x + threadIdx.x;
    if (i < NN * FDIM) {
        float f = feat[i];
        float h = h256[i];
        h256[i] = f + h * (1.f / (1.f + expf(-f)));
    }
}

__global__ void k_mean(const float* __restrict__ acc, float* __restrict__ xout, int doAdd) {
    int i = blockIdx.x * blockDim.x + threadIdx.x;
    if (i < NN * HID) {
        int n = i >> 7, d = i & 127;
        const float* a = acc + (size_t)n * FSD;
        float v = 0.25f * (a[d] + a[DH + d] + a[2 * DH + d] + a[3 * DH + d]);
        if (doAdd) xout[i] += v;
        else xout[i] = v;
    }
}

// ------------------- batch norm -------------------
__global__ void k_bnstats(const float* __restrict__ h, float* __restrict__ bsum,
                          float* __restrict__ bsq) {
    __shared__ float s1[256], s2[256];
    int tid = threadIdx.x;
    int c = tid & 127;
    int half = tid >> 7;
    int rbeg = blockIdx.x * 128;
    int rend = rbeg + 128;
    if (rend > NN) rend = NN;
    float sm = 0.f, sq = 0.f;
    for (int r = rbeg + half; r < rend; r += 2) {
        float v = h[(size_t)r * HID + c];
        sm += v;
        sq += v * v;
    }
    s1[tid] = sm;
    s2[tid] = sq;
    __syncthreads();
    if (tid < 128) {
        atomicAdd(&bsum[c], s1[tid] + s1[tid + 128]);
        atomicAdd(&bsq[c], s2[tid] + s2[tid + 128]);
    }
}

__global__ void k_bnapply(const float* __restrict__ h, const float* __restrict__ bsum,
                          const float* __restrict__ bsq, const float* __restrict__ gamma,
                          const float* __restrict__ beta, float* __restrict__ out) {
    int i = blockIdx.x * blockDim.x + threadIdx.x;
    if (i < NN * HID) {
        int c = i & 127;
        float mu = bsum[c] * (1.f / NN);
        float var = bsq[c] * (1.f / NN) - mu * mu;
        out[i] = gamma[c] * (h[i] - mu) * rsqrtf(var + EPSB) + beta[c];
    }
}

// ------------------- launch -------------------
extern "C" void kernel_launch(void* const* d_in, const int* in_sizes, int n_in,
                              void* d_out, int out_size) {
    const float* feature  = (const float*)d_in[0];
    const float* ew_f     = (const float*)d_in[1];
    const float* ew_b     = (const float*)d_in[2];
    const float* W_id     = (const float*)d_in[3];
    const float* b_id     = (const float*)d_in[4];
    const float* W_gcnf   = (const float*)d_in[5];
    const float* b_gcnf   = (const float*)d_in[6];
    const float* W_gcnb   = (const float*)d_in[7];
    const float* b_gcnb   = (const float*)d_in[8];
    const float* W1       = (const float*)d_in[9];
    const float* b1       = (const float*)d_in[10];
    const float* gat_W    = (const float*)d_in[11];
    const float* gat_al   = (const float*)d_in[12];
    const float* gat_ar   = (const float*)d_in[13];
    const float* bn_gamma = (const float*)d_in[14];
    const float* bn_beta  = (const float*)d_in[15];
    const int*   src      = (const int*)d_in[16];
    const int*   dst      = (const int*)d_in[17];
    float* out = (float*)d_out;

    float *p_h256, *p_agg, *p_hidden, *p_x, *p_fsf, *p_fsb, *p_acc;
    float *p_elf, *p_erf, *p_elb, *p_erb, *p_mf, *p_sf, *p_mb, *p_sb, *p_bsum, *p_bsq;
    int *p_cin, *p_cout, *p_iin, *p_iout, *p_ein, *p_eout;
    cudaGetSymbolAddress((void**)&p_h256, g_h256);
    cudaGetSymbolAddress((void**)&p_agg, g_agg);
    cudaGetSymbolAddress((void**)&p_hidden, g_hidden);
    cudaGetSymbolAddress((void**)&p_x, g_x);
    cudaGetSymbolAddress((void**)&p_fsf, g_fsf);
    cudaGetSymbolAddress((void**)&p_fsb, g_fsb);
    cudaGetSymbolAddress((void**)&p_acc, g_acc);
    cudaGetSymbolAddress((void**)&p_elf, g_elf);
    cudaGetSymbolAddress((void**)&p_erf, g_erf);
    cudaGetSymbolAddress((void**)&p_elb, g_elb);
    cudaGetSymbolAddress((void**)&p_erb, g_erb);
    cudaGetSymbolAddress((void**)&p_mf, g_mf);
    cudaGetSymbolAddress((void**)&p_sf, g_sf);
    cudaGetSymbolAddress((void**)&p_mb, g_mb);
    cudaGetSymbolAddress((void**)&p_sb, g_sb);
    cudaGetSymbolAddress((void**)&p_bsum, g_bsum);
    cudaGetSymbolAddress((void**)&p_bsq, g_bsq);
    cudaGetSymbolAddress((void**)&p_cin, g_cin);
    cudaGetSymbolAddress((void**)&p_cout, g_cout);
    cudaGetSymbolAddress((void**)&p_iin, g_iin);
    cudaGetSymbolAddress((void**)&p_iout, g_iout);
    cudaGetSymbolAddress((void**)&p_ein, g_ein);
    cudaGetSymbolAddress((void**)&p_eout, g_eout);

    const int EB = (NE + 255) / 256;
    const int NB = (NN + 255) / 256;
    const int NHB = (NN * HID + 255) / 256;
    const int NFB = (NN * FDIM + 255) / 256;
    const int WARPB = (NN * 32 + 127) / 128;
    const int MB = (NN + BM - 1) / BM;

    // --- CSR build (both directions) ---
    k_zeroi<<<NB, 256>>>(p_cin, NN);
    k_zeroi<<<NB, 256>>>(p_cout, NN);
    k_hist<<<EB, 256>>>(src, dst, p_cin, p_cout);
    k_scan<<<1, 1024>>>(p_cin, p_iin);
    k_scan<<<1, 1024>>>(p_cout, p_iout);
    k_zeroi<<<NB, 256>>>(p_cin, NN);
    k_zeroi<<<NB, 256>>>(p_cout, NN);
    k_scatter<<<EB, 256>>>(dst, p_iin, p_cin, p_ein);
    k_scatter<<<EB, 256>>>(src, p_iout, p_cout, p_eout);

    // --- Identity layer: lin + fwd WGCN + bwd WGCN ---
    {
        dim3 g(FDIM / BN, MB);
        k_gemm<<<g, 256>>>(feature, W_id, b_id, p_h256, NN, FDIM, FDIM, 0, 0);
        k_wgcn<<<NN, 256>>>(feature, ew_f, p_iin, p_ein, src, p_agg);
        k_gemm<<<g, 256>>>(p_agg, W_gcnf, b_gcnf, p_h256, NN, FDIM, FDIM, 1, 1);
        k_wgcn<<<NN, 256>>>(feature, ew_b, p_iout, p_eout, dst, p_agg);
        k_gemm<<<g, 256>>>(p_agg, W_gcnb, b_gcnb, p_h256, NN, FDIM, FDIM, 1, 1);
        k_idcombine<<<NFB, 256>>>(feature, p_h256);
        dim3 g1(HID / BN, MB);
        k_gemm<<<g1, 256>>>(p_h256, W1, b1, p_hidden, NN, HID, FDIM, 0, 0);
    }

    // --- 2 layers x 2 GAT blocks ---
    for (int l = 0; l < 2; l++) {
        const float* xin = p_hidden;
        for (int blk = 0; blk < 2; blk++) {
            int base = (l * 2 + blk) * 2;
            const float* Wf = gat_W + (size_t)(base + 0) * HID * FSD;
            const float* Wb = gat_W + (size_t)(base + 1) * HID * FSD;
            const float* alf = gat_al + (size_t)(base + 0) * HEADS * DH;
            const float* arf = gat_ar + (size_t)(base + 0) * HEADS * DH;
            const float* alb = gat_al + (size_t)(base + 1) * HEADS * DH;
            const float* arb = gat_ar + (size_t)(base + 1) * HEADS * DH;

            dim3 g(FSD / BN, MB);
            k_gemm<<<g, 256>>>(xin, Wf, (const float*)0, p_fsf, NN, FSD, HID, 0, 0);
            k_gemm<<<g, 256>>>(xin, Wb, (const float*)0, p_fsb, NN, FSD, HID, 0, 0);
            k_elr<<<WARPB, 128>>>(p_fsf, alf, arf, p_elf, p_erf);
            k_elr<<<WARPB, 128>>>(p_fsb, alb, arb, p_elb, p_erb);
            k_stats<<<WARPB, 128>>>(p_iin, p_ein, src, p_elf, p_erf, p_mf, p_sf);
            k_stats<<<WARPB, 128>>>(p_iout, p_eout, dst, p_elb, p_erb, p_mb, p_sb);
            k_gat_agg<<<NN, 128>>>(p_fsf, p_elf, p_erf, p_mf, p_sf, p_iin, p_ein, src, p_acc, 0);
            k_gat_agg<<<NN, 128>>>(p_fsb, p_elb, p_erb, p_mb, p_sb, p_iout, p_eout, dst, p_acc, 1);
            if (blk == 0) {
                k_mean<<<NHB, 256>>>(p_acc, p_x, 0);
                xin = p_x;
            } else {
                k_mean<<<NHB, 256>>>(p_acc, p_hidden, 1);
            }
        }
    }

    // --- BatchNorm ---
    k_zerof<<<1, 128>>>(p_bsum, HID);
    k_zerof<<<1, 128>>>(p_bsq, HID);
    k_bnstats<<<(NN + 127) / 128, 256>>>(p_hidden, p_bsum, p_bsq);
    k_bnapply<<<NHB, 256>>>(p_hidden, p_bsum, p_bsq, bn_gamma, bn_beta, out);
}

// round 5
// speedup vs baseline: 1.6012x; 1.1211x over previous
#include <cuda_runtime.h>
#include <math.h>
#include <stdint.h>

#define NN 20000
#define NE 160000
#define FDIM 256
#define HID 128
#define HEADS 4
#define DH 128
#define FSD 512
#define EPSB 1e-5f

// ------------------- device scratch (no allocations allowed) -------------------
__device__ float g_h256[NN * FDIM];
__device__ float g_agg[NN * FDIM];
__device__ float g_hidden[NN * HID];
__device__ float g_x[NN * HID];
__device__ float g_fsf[NN * FSD];
__device__ float g_fsb[NN * FSD];
__device__ float g_elf[NN * HEADS], g_erf[NN * HEADS];
__device__ float g_elb[NN * HEADS], g_erb[NN * HEADS];
__device__ int   g_cin[NN], g_cout[NN];
__device__ int   g_iin[NN + 1], g_iout[NN + 1];
__device__ int   g_ein[NE], g_eout[NE];
__device__ float g_bsum[HID], g_bsq[HID];

// ------------------- small utility kernels -------------------
__global__ void k_zeroi(int* p, int n) {
    int i = blockIdx.x * blockDim.x + threadIdx.x;
    if (i < n) p[i] = 0;
}
__global__ void k_zerof(float* p, int n) {
    int i = blockIdx.x * blockDim.x + threadIdx.x;
    if (i < n) p[i] = 0.f;
}

// ------------------- CSR build -------------------
__global__ void k_hist(const int* __restrict__ src, const int* __restrict__ dst,
                       int* __restrict__ cin, int* __restrict__ cout) {
    int e = blockIdx.x * blockDim.x + threadIdx.x;
    if (e < NE) {
        atomicAdd(&cin[dst[e]], 1);
        atomicAdd(&cout[src[e]], 1);
    }
}

__global__ void k_scan(const int* __restrict__ cnt, int* __restrict__ indptr) {
    __shared__ int ssum[1024];
    const int CH = 20;
    int tid = threadIdx.x;
    int base = tid * CH;
    int s = 0;
    for (int i = 0; i < CH; i++)
        if (base + i < NN) s += cnt[base + i];
    ssum[tid] = s;
    __syncthreads();
    for (int off = 1; off < 1024; off <<= 1) {
        int v = (tid >= off) ? ssum[tid - off] : 0;
        __syncthreads();
        ssum[tid] += v;
        __syncthreads();
    }
    int run = (tid == 0) ? 0 : ssum[tid - 1];
    for (int i = 0; i < CH; i++) {
        if (base + i < NN) {
            indptr[base + i] = run;
            run += cnt[base + i];
        }
    }
    if (tid == 1023) indptr[NN] = ssum[1023];
}

__global__ void k_scatter(const int* __restrict__ key, const int* __restrict__ indptr,
                          int* __restrict__ cur, int* __restrict__ eidx) {
    int e = blockIdx.x * blockDim.x + threadIdx.x;
    if (e < NE) {
        int k = key[e];
        int p = indptr[k] + atomicAdd(&cur[k], 1);
        eidx[p] = e;
    }
}

// ------------------- weighted GCN aggregation -------------------
__global__ void k_wgcn(const float* __restrict__ feat, const float* __restrict__ ew,
                       const int* __restrict__ indptr, const int* __restrict__ eidx,
                       const int* __restrict__ other, float* __restrict__ agg) {
    int n = blockIdx.x;
    int tid = threadIdx.x;  // 256 = FDIM
    int beg = indptr[n], end = indptr[n + 1];
    float acc = 0.f;
    for (int j = beg; j < end; j++) {
        int e = eidx[j];
        float w = ew[e];
        int u = other[e];
        acc += w * feat[(size_t)u * FDIM + tid];
    }
    agg[(size_t)n * FDIM + tid] = acc;
}

// ------------------- TF32 tensor-core GEMM: C = [C +] act(A@B + bias) -------------------
// BM=128, BN=64, BK=32. 8 warps as 4(m) x 2(n); warp tile 32x32 via m16n8k8.
// Optional second (B2, C2): grid.x doubled; blocks with bx >= ntiles use the pair.
#define BM 128
#define BN 64
#define BK 32
#define APAD 4
#define BPAD 8

__device__ __forceinline__ uint32_t f2tf32(float x) {
    uint32_t y;
    asm("cvt.rna.tf32.f32 %0, %1;" : "=r"(y) : "f"(x));
    return y;
}

__device__ __forceinline__ void mma_tf32(float* c, uint32_t a0, uint32_t a1,
                                         uint32_t a2, uint32_t a3,
                                         uint32_t b0, uint32_t b1) {
    asm volatile(
        "mma.sync.aligned.m16n8k8.row.col.f32.tf32.tf32.f32 "
        "{%0,%1,%2,%3}, {%4,%5,%6,%7}, {%8,%9}, {%0,%1,%2,%3};"
        : "+f"(c[0]), "+f"(c[1]), "+f"(c[2]), "+f"(c[3])
        : "r"(a0), "r"(a1), "r"(a2), "r"(a3), "r"(b0), "r"(b1));
}

__global__ __launch_bounds__(256, 2)
void k_gemm(const float* __restrict__ A, const float* __restrict__ Bp,
            const float* __restrict__ bias, float* __restrict__ Cp,
            int M, int N, int K, int doAcc, int doRelu,
            const float* __restrict__ B2, float* __restrict__ C2, int ntiles) {
    __shared__ uint32_t As[BM][BK + APAD];   // [m][k] tf32 bits
    __shared__ uint32_t Bs[BK][BN + BPAD];   // [k][n] tf32 bits
    const float* B = Bp;
    float* C = Cp;
    int bx = blockIdx.x;
    if (B2 != 0 && bx >= ntiles) { B = B2; C = C2; bx -= ntiles; }
    int bm = blockIdx.y * BM;
    int bn = bx * BN;
    int tid = threadIdx.x;
    int wid = tid >> 5, lane = tid & 31;
    int wm = (wid >> 1) * 32;   // 0,32,64,96
    int wn = (wid & 1) * 32;    // 0,32
    int grp = lane >> 2, tig = lane & 3;

    float c[2][4][4];
#pragma unroll
    for (int im = 0; im < 2; im++)
#pragma unroll
        for (int jn = 0; jn < 4; jn++)
#pragma unroll
            for (int r = 0; r < 4; r++) c[im][jn][r] = 0.f;

    int ar[4], ac[4];
#pragma unroll
    for (int i = 0; i < 4; i++) {
        int idx = tid + 256 * i;
        ar[i] = idx >> 3;
        ac[i] = (idx & 7) * 4;
    }
    int br[2], bc[2];
#pragma unroll
    for (int i = 0; i < 2; i++) {
        int idx = tid + 256 * i;
        br[i] = idx >> 4;
        bc[i] = (idx & 15) * 4;
    }

    float4 pa[4], pb[2];
#pragma unroll
    for (int i = 0; i < 4; i++) {
        int m = bm + ar[i]; if (m >= M) m = M - 1;
        pa[i] = *(const float4*)&A[(size_t)m * K + ac[i]];
    }
#pragma unroll
    for (int i = 0; i < 2; i++)
        pb[i] = *(const float4*)&B[(size_t)br[i] * N + bn + bc[i]];

    for (int k0 = 0; k0 < K; k0 += BK) {
#pragma unroll
        for (int i = 0; i < 4; i++) {
            As[ar[i]][ac[i] + 0] = f2tf32(pa[i].x);
            As[ar[i]][ac[i] + 1] = f2tf32(pa[i].y);
            As[ar[i]][ac[i] + 2] = f2tf32(pa[i].z);
            As[ar[i]][ac[i] + 3] = f2tf32(pa[i].w);
        }
#pragma unroll
        for (int i = 0; i < 2; i++) {
            Bs[br[i]][bc[i] + 0] = f2tf32(pb[i].x);
            Bs[br[i]][bc[i] + 1] = f2tf32(pb[i].y);
            Bs[br[i]][bc[i] + 2] = f2tf32(pb[i].z);
            Bs[br[i]][bc[i] + 3] = f2tf32(pb[i].w);
        }
        __syncthreads();
        if (k0 + BK < K) {
#pragma unroll
            for (int i = 0; i < 4; i++) {
                int m = bm + ar[i]; if (m >= M) m = M - 1;
                pa[i] = *(const float4*)&A[(size_t)m * K + k0 + BK + ac[i]];
            }
#pragma unroll
            for (int i = 0; i < 2; i++)
                pb[i] = *(const float4*)&B[(size_t)(k0 + BK + br[i]) * N + bn + bc[i]];
        }
#pragma unroll
        for (int ks = 0; ks < BK / 8; ks++) {
            int kk = ks * 8;
            uint32_t af[2][4], bf[4][2];
#pragma unroll
            for (int im = 0; im < 2; im++) {
                int mb_ = wm + im * 16;
                af[im][0] = As[mb_ + grp][kk + tig];
                af[im][1] = As[mb_ + 8 + grp][kk + tig];
                af[im][2] = As[mb_ + grp][kk + tig + 4];
                af[im][3] = As[mb_ + 8 + grp][kk + tig + 4];
            }
#pragma unroll
            for (int jn = 0; jn < 4; jn++) {
                int nb_ = wn + jn * 8;
                bf[jn][0] = Bs[kk + tig][nb_ + grp];
                bf[jn][1] = Bs[kk + tig + 4][nb_ + grp];
            }
#pragma unroll
            for (int im = 0; im < 2; im++)
#pragma unroll
                for (int jn = 0; jn < 4; jn++)
                    mma_tf32(c[im][jn], af[im][0], af[im][1], af[im][2], af[im][3],
                             bf[jn][0], bf[jn][1]);
        }
        __syncthreads();
    }

#pragma unroll
    for (int im = 0; im < 2; im++) {
#pragma unroll
        for (int half = 0; half < 2; half++) {
            int m = bm + wm + im * 16 + grp + half * 8;
            if (m >= M) continue;
#pragma unroll
            for (int jn = 0; jn < 4; jn++) {
                int col = bn + wn + jn * 8 + 2 * tig;
                float v0 = c[im][jn][half * 2 + 0];
                float v1 = c[im][jn][half * 2 + 1];
                if (bias) {
                    float2 bb = *(const float2*)&bias[col];
                    v0 += bb.x; v1 += bb.y;
                }
                if (doRelu) {
                    v0 = v0 > 0.f ? v0 : 0.f;
                    v1 = v1 > 0.f ? v1 : 0.f;
                }
                float* cp = C + (size_t)m * N + col;
                if (doAcc) {
                    float2 cv = *(const float2*)cp;
                    v0 += cv.x; v1 += cv.y;
                }
                *(float2*)cp = make_float2(v0, v1);
            }
        }
    }
}

// ------------------- GAT attention logits (both directions in one launch) -------------------
__global__ void k_elr2(const float* __restrict__ fsf, const float* __restrict__ alf,
                       const float* __restrict__ arf, const float* __restrict__ fsb,
                       const float* __restrict__ alb, const float* __restrict__ arb,
                       float* __restrict__ elf, float* __restrict__ erf,
                       float* __restrict__ elb, float* __restrict__ erb) {
    int w = (blockIdx.x * blockDim.x + threadIdx.x) >> 5;
    int lane = threadIdx.x & 31;
    if (w >= NN) return;
#pragma unroll
    for (int dir = 0; dir < 2; dir++) {
        const float* f = (dir ? fsb : fsf) + (size_t)w * FSD;
        const float* al = dir ? alb : alf;
        const float* ar = dir ? arb : arf;
        float* el = dir ? elb : elf;
        float* er = dir ? erb : erf;
#pragma unroll
        for (int h = 0; h < HEADS; h++) {
            float sl = 0.f, sr = 0.f;
#pragma unroll
            for (int d = lane; d < DH; d += 32) {
                float v = f[h * DH + d];
                sl += v * al[h * DH + d];
                sr += v * ar[h * DH + d];
            }
#pragma unroll
            for (int off = 16; off > 0; off >>= 1) {
                sl += __shfl_xor_sync(0xffffffffu, sl, off);
                sr += __shfl_xor_sync(0xffffffffu, sr, off);
            }
            if (lane == 0) { el[w * HEADS + h] = sl; er[w * HEADS + h] = sr; }
        }
    }
}

// ------------------- fused GAT block: softmax stats + fwd&bwd aggregation + head-mean -------
// One block (128 thr) per node. xout[n,:] = 0.25*sum_h(aggf+aggb) (+ xout residual)
__global__ __launch_bounds__(128)
void k_gatblock(const float* __restrict__ fsf, const float* __restrict__ fsb,
                const float* __restrict__ elf, const float* __restrict__ erf,
                const float* __restrict__ elb, const float* __restrict__ erb,
                const int* __restrict__ iin, const int* __restrict__ ein,
                const int* __restrict__ srcv,
                const int* __restrict__ iout, const int* __restrict__ eout,
                const int* __restrict__ dstv,
                float* __restrict__ xout, int doResid) {
    int n = blockIdx.x;
    int tid = threadIdx.x;          // 128 = DH
    int wid = tid >> 5, lane = tid & 31;
    __shared__ float sm[HEADS], ssv[HEADS];
    __shared__ float wsh[32][HEADS];
    __shared__ int ush[32];

    float rtot[HEADS] = {0.f, 0.f, 0.f, 0.f};

#pragma unroll
    for (int dir = 0; dir < 2; dir++) {
        const float* fs = dir ? fsb : fsf;
        const float* el = dir ? elb : elf;
        const float* er = dir ? erb : erf;
        const int* indptr = dir ? iout : iin;
        const int* eidx = dir ? eout : ein;
        const int* other = dir ? dstv : srcv;
        int beg = indptr[n], end = indptr[n + 1];
        if (beg < end) {
            // --- stats: warp wid handles head wid ---
            {
                int h = wid;
                float ern = er[n * HEADS + h];
                float mh = -1e30f;
                for (int j = beg + lane; j < end; j += 32) {
                    int u = other[eidx[j]];
                    float e = el[u * HEADS + h] + ern;
                    e = e > 0.f ? e : 0.2f * e;
                    mh = fmaxf(mh, e);
                }
#pragma unroll
                for (int off = 16; off > 0; off >>= 1)
                    mh = fmaxf(mh, __shfl_xor_sync(0xffffffffu, mh, off));
                float sh = 0.f;
                for (int j = beg + lane; j < end; j += 32) {
                    int u = other[eidx[j]];
                    float e = el[u * HEADS + h] + ern;
                    e = e > 0.f ? e : 0.2f * e;
                    sh += expf(e - mh);
                }
#pragma unroll
                for (int off = 16; off > 0; off >>= 1)
                    sh += __shfl_xor_sync(0xffffffffu, sh, off);
                if (lane == 0) { sm[h] = mh; ssv[h] = 1.f / sh; }
            }
            __syncthreads();
            float ern4[HEADS], mh4[HEADS], sv4[HEADS];
#pragma unroll
            for (int h = 0; h < HEADS; h++) {
                ern4[h] = er[n * HEADS + h];
                mh4[h] = sm[h];
                sv4[h] = ssv[h];
            }
            // --- weighted aggregation in 32-edge chunks ---
            for (int c = beg; c < end; c += 32) {
                int ne = end - c;
                if (ne > 32) ne = 32;
                if (tid < ne * HEADS) {
                    int j = tid >> 2, h = tid & 3;
                    int e = eidx[c + j];
                    int u = other[e];
                    if (h == 0) ush[j] = u;
                    float ev = el[u * HEADS + h] + ern4[h];
                    ev = ev > 0.f ? ev : 0.2f * ev;
                    wsh[j][h] = expf(ev - mh4[h]) * sv4[h];
                }
                __syncthreads();
                for (int j = 0; j < ne; j++) {
                    int u = ush[j];
                    const float* frow = fs + (size_t)u * FSD;
#pragma unroll
                    for (int h = 0; h < HEADS; h++)
                        rtot[h] += wsh[j][h] * frow[h * DH + tid];
                }
                __syncthreads();
            }
        }
        __syncthreads();  // protect sm/ssv reuse across directions
    }

    float v = 0.25f * (rtot[0] + rtot[1] + rtot[2] + rtot[3]);
    size_t oi = (size_t)n * HID + tid;
    if (doResid) v += xout[oi];
    xout[oi] = v;
}

// ------------------- elementwise glue -------------------
__global__ void k_idcombine(const float* __restrict__ feat, float* __restrict__ h256) {
    int i = blockIdx.x * blockDim.x + threadIdx.x;
    if (i < NN * FDIM) {
        float f = feat[i];
        float h = h256[i];
        h256[i] = f + h * (1.f / (1.f + expf(-f)));
    }
}

// ------------------- batch norm -------------------
__global__ void k_bnstats(const float* __restrict__ h, float* __restrict__ bsum,
                          float* __restrict__ bsq) {
    __shared__ float s1[256], s2[256];
    int tid = threadIdx.x;
    int c = tid & 127;
    int half = tid >> 7;
    int rbeg = blockIdx.x * 128;
    int rend = rbeg + 128;
    if (rend > NN) rend = NN;
    float sm = 0.f, sq = 0.f;
    for (int r = rbeg + half; r < rend; r += 2) {
        float v = h[(size_t)r * HID + c];
        sm += v;
        sq += v * v;
    }
    s1[tid] = sm;
    s2[tid] = sq;
    __syncthreads();
    if (tid < 128) {
        atomicAdd(&bsum[c], s1[tid] + s1[tid + 128]);
        atomicAdd(&bsq[c], s2[tid] + s2[tid + 128]);
    }
}

__global__ void k_bnapply(const float* __restrict__ h, const float* __restrict__ bsum,
                          const float* __restrict__ bsq, const float* __restrict__ gamma,
                          const float* __restrict__ beta, float* __restrict__ out) {
    int i = blockIdx.x * blockDim.x + threadIdx.x;
    if (i < NN * HID) {
        int c = i & 127;
        float mu = bsum[c] * (1.f / NN);
        float var = bsq[c] * (1.f / NN) - mu * mu;
        out[i] = gamma[c] * (h[i] - mu) * rsqrtf(var + EPSB) + beta[c];
    }
}

// ------------------- launch -------------------
extern "C" void kernel_launch(void* const* d_in, const int* in_sizes, int n_in,
                              void* d_out, int out_size) {
    const float* feature  = (const float*)d_in[0];
    const float* ew_f     = (const float*)d_in[1];
    const float* ew_b     = (const float*)d_in[2];
    const float* W_id     = (const float*)d_in[3];
    const float* b_id     = (const float*)d_in[4];
    const float* W_gcnf   = (const float*)d_in[5];
    const float* b_gcnf   = (const float*)d_in[6];
    const float* W_gcnb   = (const float*)d_in[7];
    const float* b_gcnb   = (const float*)d_in[8];
    const float* W1       = (const float*)d_in[9];
    const float* b1       = (const float*)d_in[10];
    const float* gat_W    = (const float*)d_in[11];
    const float* gat_al   = (const float*)d_in[12];
    const float* gat_ar   = (const float*)d_in[13];
    const float* bn_gamma = (const float*)d_in[14];
    const float* bn_beta  = (const float*)d_in[15];
    const int*   src      = (const int*)d_in[16];
    const int*   dst      = (const int*)d_in[17];
    float* out = (float*)d_out;

    float *p_h256, *p_agg, *p_hidden, *p_x, *p_fsf, *p_fsb;
    float *p_elf, *p_erf, *p_elb, *p_erb, *p_bsum, *p_bsq;
    int *p_cin, *p_cout, *p_iin, *p_iout, *p_ein, *p_eout;
    cudaGetSymbolAddress((void**)&p_h256, g_h256);
    cudaGetSymbolAddress((void**)&p_agg, g_agg);
    cudaGetSymbolAddress((void**)&p_hidden, g_hidden);
    cudaGetSymbolAddress((void**)&p_x, g_x);
    cudaGetSymbolAddress((void**)&p_fsf, g_fsf);
    cudaGetSymbolAddress((void**)&p_fsb, g_fsb);
    cudaGetSymbolAddress((void**)&p_elf, g_elf);
    cudaGetSymbolAddress((void**)&p_erf, g_erf);
    cudaGetSymbolAddress((void**)&p_elb, g_elb);
    cudaGetSymbolAddress((void**)&p_erb, g_erb);
    cudaGetSymbolAddress((void**)&p_bsum, g_bsum);
    cudaGetSymbolAddress((void**)&p_bsq, g_bsq);
    cudaGetSymbolAddress((void**)&p_cin, g_cin);
    cudaGetSymbolAddress((void**)&p_cout, g_cout);
    cudaGetSymbolAddress((void**)&p_iin, g_iin);
    cudaGetSymbolAddress((void**)&p_iout, g_iout);
    cudaGetSymbolAddress((void**)&p_ein, g_ein);
    cudaGetSymbolAddress((void**)&p_eout, g_eout);

    const int EB = (NE + 255) / 256;
    const int NB = (NN + 255) / 256;
    const int NHB = (NN * HID + 255) / 256;
    const int NFB = (NN * FDIM + 255) / 256;
    const int WARPB = (NN * 32 + 127) / 128;
    const int MB = (NN + BM - 1) / BM;

    // --- CSR build (both directions) ---
    k_zeroi<<<NB, 256>>>(p_cin, NN);
    k_zeroi<<<NB, 256>>>(p_cout, NN);
    k_hist<<<EB, 256>>>(src, dst, p_cin, p_cout);
    k_scan<<<1, 1024>>>(p_cin, p_iin);
    k_scan<<<1, 1024>>>(p_cout, p_iout);
    k_zeroi<<<NB, 256>>>(p_cin, NN);
    k_zeroi<<<NB, 256>>>(p_cout, NN);
    k_scatter<<<EB, 256>>>(dst, p_iin, p_cin, p_ein);
    k_scatter<<<EB, 256>>>(src, p_iout, p_cout, p_eout);

    // --- Identity layer: lin + fwd WGCN + bwd WGCN ---
    {
        dim3 g(FDIM / BN, MB);
        k_gemm<<<g, 256>>>(feature, W_id, b_id, p_h256, NN, FDIM, FDIM, 0, 0,
                           (const float*)0, (float*)0, FDIM / BN);
        k_wgcn<<<NN, 256>>>(feature, ew_f, p_iin, p_ein, src, p_agg);
        k_gemm<<<g, 256>>>(p_agg, W_gcnf, b_gcnf, p_h256, NN, FDIM, FDIM, 1, 1,
                           (const float*)0, (float*)0, FDIM / BN);
        k_wgcn<<<NN, 256>>>(feature, ew_b, p_iout, p_eout, dst, p_agg);
        k_gemm<<<g, 256>>>(p_agg, W_gcnb, b_gcnb, p_h256, NN, FDIM, FDIM, 1, 1,
                           (const float*)0, (float*)0, FDIM / BN);
        k_idcombine<<<NFB, 256>>>(feature, p_h256);
        dim3 g1(HID / BN, MB);
        k_gemm<<<g1, 256>>>(p_h256, W1, b1, p_hidden, NN, HID, FDIM, 0, 0,
                            (const float*)0, (float*)0, HID / BN);
    }

    // --- 2 layers x 2 GAT blocks ---
    for (int l = 0; l < 2; l++) {
        const float* xin = p_hidden;
        for (int blk = 0; blk < 2; blk++) {
            int base = (l * 2 + blk) * 2;
            const float* Wf = gat_W + (size_t)(base + 0) * HID * FSD;
            const float* Wb = gat_W + (size_t)(base + 1) * HID * FSD;
            const float* alf = gat_al + (size_t)(base + 0) * HEADS * DH;
            const float* arf = gat_ar + (size_t)(base + 0) * HEADS * DH;
            const float* alb = gat_al + (size_t)(base + 1) * HEADS * DH;
            const float* arb = gat_ar + (size_t)(base + 1) * HEADS * DH;

            // fsf = xin @ Wf, fsb = xin @ Wb in ONE launch (pointer-select)
            dim3 g((FSD / BN) * 2, MB);
            k_gemm<<<g, 256>>>(xin, Wf, (const float*)0, p_fsf, NN, FSD, HID, 0, 0,
                               Wb, p_fsb, FSD / BN);
            // attention logits, both directions
            k_elr2<<<WARPB, 128>>>(p_fsf, alf, arf, p_fsb, alb, arb,
                                   p_elf, p_erf, p_elb, p_erb);
            // fused: stats + fwd/bwd aggregation + head-mean (+residual for blk 1)
            if (blk == 0) {
                k_gatblock<<<NN, 128>>>(p_fsf, p_fsb, p_elf, p_erf, p_elb, p_erb,
                                        p_iin, p_ein, src, p_iout, p_eout, dst,
                                        p_x, 0);
                xin = p_x;
            } else {
                k_gatblock<<<NN, 128>>>(p_fsf, p_fsb, p_elf, p_erf, p_elb, p_erb,
                                        p_iin, p_ein, src, p_iout, p_eout, dst,
                                        p_hidden, 1);
            }
        }
    }

    // --- BatchNorm ---
    k_zerof<<<1, 128>>>(p_bsum, HID);
    k_zerof<<<1, 128>>>(p_bsq, HID);
    k_bnstats<<<(NN + 127) / 128, 256>>>(p_hidden, p_bsum, p_bsq);
    k_bnapply<<<NHB, 256>>>(p_hidden, p_bsum, p_bsq, bn_gamma, bn_beta, out);
}

// round 6
// speedup vs baseline: 1.7682x; 1.1043x over previous
#include <cuda_runtime.h>
#include <math.h>
#include <stdint.h>

#define NN 20000
#define NE 160000
#define FDIM 256
#define HID 128
#define HEADS 4
#define DH 128
#define FSD 512
#define EPSB 1e-5f

// ------------------- device scratch (no allocations allowed) -------------------
__device__ float g_h256[NN * FDIM];
__device__ float g_agg[NN * FDIM];
__device__ float g_hidden[NN * HID];
__device__ float g_x[NN * HID];
__device__ float g_fsf[NN * FSD];
__device__ float g_fsb[NN * FSD];
__device__ float g_elf[NN * HEADS], g_erf[NN * HEADS];
__device__ float g_elb[NN * HEADS], g_erb[NN * HEADS];
__device__ int   g_cin[NN], g_cout[NN];
__device__ int   g_iin[NN + 1], g_iout[NN + 1];
__device__ int   g_ein[NE], g_eout[NE];
__device__ float g_bsum[HID], g_bsq[HID];

// ------------------- small utility kernels -------------------
__global__ void k_zero2(int* a, int* b, int n) {
    int i = blockIdx.x * blockDim.x + threadIdx.x;
    if (i < n) { a[i] = 0; b[i] = 0; }
}
__global__ void k_zerof(float* p, int n) {
    int i = blockIdx.x * blockDim.x + threadIdx.x;
    if (i < n) p[i] = 0.f;
}

// ------------------- CSR build -------------------
__global__ void k_hist(const int* __restrict__ src, const int* __restrict__ dst,
                       int* __restrict__ cin, int* __restrict__ cout) {
    int e = blockIdx.x * blockDim.x + threadIdx.x;
    if (e < NE) {
        atomicAdd(&cin[dst[e]], 1);
        atomicAdd(&cout[src[e]], 1);
    }
}

// 2 blocks: block 0 scans c0->i0, block 1 scans c1->i1
__global__ void k_scan2(const int* __restrict__ c0, int* __restrict__ i0,
                        const int* __restrict__ c1, int* __restrict__ i1) {
    __shared__ int ssum[1024];
    const int CH = 20;
    const int* cnt = blockIdx.x ? c1 : c0;
    int* indptr = blockIdx.x ? i1 : i0;
    int tid = threadIdx.x;
    int base = tid * CH;
    int s = 0;
    for (int i = 0; i < CH; i++)
        if (base + i < NN) s += cnt[base + i];
    ssum[tid] = s;
    __syncthreads();
    for (int off = 1; off < 1024; off <<= 1) {
        int v = (tid >= off) ? ssum[tid - off] : 0;
        __syncthreads();
        ssum[tid] += v;
        __syncthreads();
    }
    int run = (tid == 0) ? 0 : ssum[tid - 1];
    for (int i = 0; i < CH; i++) {
        if (base + i < NN) {
            indptr[base + i] = run;
            run += cnt[base + i];
        }
    }
    if (tid == 1023) indptr[NN] = ssum[1023];
}

// both directions in one launch: grid = 2*EB
__global__ void k_scatter2(const int* __restrict__ dst, const int* __restrict__ iin,
                           int* __restrict__ cin, int* __restrict__ ein,
                           const int* __restrict__ src, const int* __restrict__ iout,
                           int* __restrict__ cout, int* __restrict__ eout) {
    int e = blockIdx.x * blockDim.x + threadIdx.x;
    if (e < NE) {
        int k = dst[e];
        int p = iin[k] + atomicAdd(&cin[k], 1);
        ein[p] = e;
    } else {
        e -= NE;
        if (e < NE) {
            int k = src[e];
            int p = iout[k] + atomicAdd(&cout[k], 1);
            eout[p] = e;
        }
    }
}

// ------------------- weighted GCN aggregation (both dirs, float4, 4 nodes/block) ------------
__global__ __launch_bounds__(256)
void k_wgcn2(const float4* __restrict__ feat4,
             const float* __restrict__ ewf, const float* __restrict__ ewb,
             const int* __restrict__ iin, const int* __restrict__ ein,
             const int* __restrict__ srcv,
             const int* __restrict__ iout, const int* __restrict__ eout,
             const int* __restrict__ dstv,
             float4* __restrict__ aggf4, float4* __restrict__ aggb4) {
    int g = threadIdx.x >> 6;       // 0..3 node group
    int t = threadIdx.x & 63;       // float4 index over 256 dims
    int n = blockIdx.x * 4 + g;
    int dir = blockIdx.y;
    if (n >= NN) return;
    const int* indptr = dir ? iout : iin;
    const int* eidx = dir ? eout : ein;
    const int* other = dir ? dstv : srcv;
    const float* ew = dir ? ewb : ewf;
    float4* agg4 = dir ? aggb4 : aggf4;
    int beg = indptr[n], end = indptr[n + 1];
    float4 acc = make_float4(0.f, 0.f, 0.f, 0.f);
    for (int j = beg; j < end; j++) {
        int e = eidx[j];
        float w = ew[e];
        int u = other[e];
        float4 v = feat4[(size_t)u * 64 + t];
        acc.x += w * v.x; acc.y += w * v.y; acc.z += w * v.z; acc.w += w * v.w;
    }
    agg4[(size_t)n * 64 + t] = acc;
}

// ------------------- TF32 tensor-core GEMM: C = [C +] act(A@B + bias) -------------------
#define BM 128
#define BN 64
#define BK 32
#define APAD 4
#define BPAD 8

__device__ __forceinline__ uint32_t f2tf32(float x) {
    uint32_t y;
    asm("cvt.rna.tf32.f32 %0, %1;" : "=r"(y) : "f"(x));
    return y;
}

__device__ __forceinline__ void mma_tf32(float* c, uint32_t a0, uint32_t a1,
                                         uint32_t a2, uint32_t a3,
                                         uint32_t b0, uint32_t b1) {
    asm volatile(
        "mma.sync.aligned.m16n8k8.row.col.f32.tf32.tf32.f32 "
        "{%0,%1,%2,%3}, {%4,%5,%6,%7}, {%8,%9}, {%0,%1,%2,%3};"
        : "+f"(c[0]), "+f"(c[1]), "+f"(c[2]), "+f"(c[3])
        : "r"(a0), "r"(a1), "r"(a2), "r"(a3), "r"(b0), "r"(b1));
}

__global__ __launch_bounds__(256, 2)
void k_gemm(const float* __restrict__ A, const float* __restrict__ Bp,
            const float* __restrict__ bias, float* __restrict__ Cp,
            int M, int N, int K, int doAcc, int doRelu,
            const float* __restrict__ B2, float* __restrict__ C2, int ntiles) {
    __shared__ uint32_t As[BM][BK + APAD];
    __shared__ uint32_t Bs[BK][BN + BPAD];
    const float* B = Bp;
    float* C = Cp;
    int bx = blockIdx.x;
    if (B2 != 0 && bx >= ntiles) { B = B2; C = C2; bx -= ntiles; }
    int bm = blockIdx.y * BM;
    int bn = bx * BN;
    int tid = threadIdx.x;
    int wid = tid >> 5, lane = tid & 31;
    int wm = (wid >> 1) * 32;
    int wn = (wid & 1) * 32;
    int grp = lane >> 2, tig = lane & 3;

    float c[2][4][4];
#pragma unroll
    for (int im = 0; im < 2; im++)
#pragma unroll
        for (int jn = 0; jn < 4; jn++)
#pragma unroll
            for (int r = 0; r < 4; r++) c[im][jn][r] = 0.f;

    int ar[4], ac[4];
#pragma unroll
    for (int i = 0; i < 4; i++) {
        int idx = tid + 256 * i;
        ar[i] = idx >> 3;
        ac[i] = (idx & 7) * 4;
    }
    int br[2], bc[2];
#pragma unroll
    for (int i = 0; i < 2; i++) {
        int idx = tid + 256 * i;
        br[i] = idx >> 4;
        bc[i] = (idx & 15) * 4;
    }

    float4 pa[4], pb[2];
#pragma unroll
    for (int i = 0; i < 4; i++) {
        int m = bm + ar[i]; if (m >= M) m = M - 1;
        pa[i] = *(const float4*)&A[(size_t)m * K + ac[i]];
    }
#pragma unroll
    for (int i = 0; i < 2; i++)
        pb[i] = *(const float4*)&B[(size_t)br[i] * N + bn + bc[i]];

    for (int k0 = 0; k0 < K; k0 += BK) {
#pragma unroll
        for (int i = 0; i < 4; i++) {
            As[ar[i]][ac[i] + 0] = f2tf32(pa[i].x);
            As[ar[i]][ac[i] + 1] = f2tf32(pa[i].y);
            As[ar[i]][ac[i] + 2] = f2tf32(pa[i].z);
            As[ar[i]][ac[i] + 3] = f2tf32(pa[i].w);
        }
#pragma unroll
        for (int i = 0; i < 2; i++) {
            Bs[br[i]][bc[i] + 0] = f2tf32(pb[i].x);
            Bs[br[i]][bc[i] + 1] = f2tf32(pb[i].y);
            Bs[br[i]][bc[i] + 2] = f2tf32(pb[i].z);
            Bs[br[i]][bc[i] + 3] = f2tf32(pb[i].w);
        }
        __syncthreads();
        if (k0 + BK < K) {
#pragma unroll
            for (int i = 0; i < 4; i++) {
                int m = bm + ar[i]; if (m >= M) m = M - 1;
                pa[i] = *(const float4*)&A[(size_t)m * K + k0 + BK + ac[i]];
            }
#pragma unroll
            for (int i = 0; i < 2; i++)
                pb[i] = *(const float4*)&B[(size_t)(k0 + BK + br[i]) * N + bn + bc[i]];
        }
#pragma unroll
        for (int ks = 0; ks < BK / 8; ks++) {
            int kk = ks * 8;
            uint32_t af[2][4], bf[4][2];
#pragma unroll
            for (int im = 0; im < 2; im++) {
                int mb_ = wm + im * 16;
                af[im][0] = As[mb_ + grp][kk + tig];
                af[im][1] = As[mb_ + 8 + grp][kk + tig];
                af[im][2] = As[mb_ + grp][kk + tig + 4];
                af[im][3] = As[mb_ + 8 + grp][kk + tig + 4];
            }
#pragma unroll
            for (int jn = 0; jn < 4; jn++) {
                int nb_ = wn + jn * 8;
                bf[jn][0] = Bs[kk + tig][nb_ + grp];
                bf[jn][1] = Bs[kk + tig + 4][nb_ + grp];
            }
#pragma unroll
            for (int im = 0; im < 2; im++)
#pragma unroll
                for (int jn = 0; jn < 4; jn++)
                    mma_tf32(c[im][jn], af[im][0], af[im][1], af[im][2], af[im][3],
                             bf[jn][0], bf[jn][1]);
        }
        __syncthreads();
    }

#pragma unroll
    for (int im = 0; im < 2; im++) {
#pragma unroll
        for (int half = 0; half < 2; half++) {
            int m = bm + wm + im * 16 + grp + half * 8;
            if (m >= M) continue;
#pragma unroll
            for (int jn = 0; jn < 4; jn++) {
                int col = bn + wn + jn * 8 + 2 * tig;
                float v0 = c[im][jn][half * 2 + 0];
                float v1 = c[im][jn][half * 2 + 1];
                if (bias) {
                    float2 bb = *(const float2*)&bias[col];
                    v0 += bb.x; v1 += bb.y;
                }
                if (doRelu) {
                    v0 = v0 > 0.f ? v0 : 0.f;
                    v1 = v1 > 0.f ? v1 : 0.f;
                }
                float* cp = C + (size_t)m * N + col;
                if (doAcc) {
                    float2 cv = *(const float2*)cp;
                    v0 += cv.x; v1 += cv.y;
                }
                *(float2*)cp = make_float2(v0, v1);
            }
        }
    }
}

// ------------------- GAT attention logits (both directions in one launch) -------------------
__global__ void k_elr2(const float* __restrict__ fsf, const float* __restrict__ alf,
                       const float* __restrict__ arf, const float* __restrict__ fsb,
                       const float* __restrict__ alb, const float* __restrict__ arb,
                       float* __restrict__ elf, float* __restrict__ erf,
                       float* __restrict__ elb, float* __restrict__ erb) {
    int w = (blockIdx.x * blockDim.x + threadIdx.x) >> 5;
    int lane = threadIdx.x & 31;
    if (w >= NN) return;
#pragma unroll
    for (int dir = 0; dir < 2; dir++) {
        const float* f = (dir ? fsb : fsf) + (size_t)w * FSD;
        const float* al = dir ? alb : alf;
        const float* ar = dir ? arb : arf;
        float* el = dir ? elb : elf;
        float* er = dir ? erb : erf;
#pragma unroll
        for (int h = 0; h < HEADS; h++) {
            float sl = 0.f, sr = 0.f;
#pragma unroll
            for (int d = lane; d < DH; d += 32) {
                float v = f[h * DH + d];
                sl += v * al[h * DH + d];
                sr += v * ar[h * DH + d];
            }
#pragma unroll
            for (int off = 16; off > 0; off >>= 1) {
                sl += __shfl_xor_sync(0xffffffffu, sl, off);
                sr += __shfl_xor_sync(0xffffffffu, sr, off);
            }
            if (lane == 0) { el[w * HEADS + h] = sl; er[w * HEADS + h] = sr; }
        }
    }
}

// ------------------- fused GAT block: stats + fwd&bwd aggregation + head-mean ---------------
// warp = head, lane = float4 over D. One block (128 thr) per node.
__global__ __launch_bounds__(128)
void k_gatblock(const float* __restrict__ fsf, const float* __restrict__ fsb,
                const float* __restrict__ elf, const float* __restrict__ erf,
                const float* __restrict__ elb, const float* __restrict__ erb,
                const int* __restrict__ iin, const int* __restrict__ ein,
                const int* __restrict__ srcv,
                const int* __restrict__ iout, const int* __restrict__ eout,
                const int* __restrict__ dstv,
                float* __restrict__ xout, int doResid) {
    int n = blockIdx.x;
    int tid = threadIdx.x;
    int wid = tid >> 5, lane = tid & 31;
    __shared__ float sm[HEADS], ssv[HEADS];
    __shared__ float wsh[32][HEADS];
    __shared__ int ush[32];
    __shared__ float sred[HEADS][DH];

    float4 rf = make_float4(0.f, 0.f, 0.f, 0.f);  // head=wid, d=4*lane..+3
    int myh = tid & 3;

#pragma unroll
    for (int dir = 0; dir < 2; dir++) {
        const float* fs = dir ? fsb : fsf;
        const float* el = dir ? elb : elf;
        const float* er = dir ? erb : erf;
        const int* indptr = dir ? iout : iin;
        const int* eidx = dir ? eout : ein;
        const int* other = dir ? dstv : srcv;
        int beg = indptr[n], end = indptr[n + 1];
        if (beg < end) {
            // stats: warp wid handles head wid
            {
                int h = wid;
                float ern = er[n * HEADS + h];
                float mh = -1e30f;
                for (int j = beg + lane; j < end; j += 32) {
                    int u = other[eidx[j]];
                    float e = el[u * HEADS + h] + ern;
                    e = e > 0.f ? e : 0.2f * e;
                    mh = fmaxf(mh, e);
                }
#pragma unroll
                for (int off = 16; off > 0; off >>= 1)
                    mh = fmaxf(mh, __shfl_xor_sync(0xffffffffu, mh, off));
                float sh = 0.f;
                for (int j = beg + lane; j < end; j += 32) {
                    int u = other[eidx[j]];
                    float e = el[u * HEADS + h] + ern;
                    e = e > 0.f ? e : 0.2f * e;
                    sh += expf(e - mh);
                }
#pragma unroll
                for (int off = 16; off > 0; off >>= 1)
                    sh += __shfl_xor_sync(0xffffffffu, sh, off);
                if (lane == 0) { sm[h] = mh; ssv[h] = 1.f / sh; }
            }
            __syncthreads();
            float ernh = er[n * HEADS + myh];
            float mhh = sm[myh];
            float svh = ssv[myh];
            const float* fsh = fs + (size_t)wid * DH;  // head base
            for (int c = beg; c < end; c += 32) {
                int ne = end - c;
                if (ne > 32) ne = 32;
                if (tid < ne * HEADS) {
                    int j = tid >> 2;
                    int e = eidx[c + j];
                    int u = other[e];
                    if (myh == 0) ush[j] = u;
                    float ev = el[u * HEADS + myh] + ernh;
                    ev = ev > 0.f ? ev : 0.2f * ev;
                    wsh[j][myh] = expf(ev - mhh) * svh;
                }
                __syncthreads();
#pragma unroll 4
                for (int j = 0; j < ne; j++) {
                    int u = ush[j];
                    float w = wsh[j][wid];
                    float4 v = *(const float4*)(fsh + (size_t)u * FSD + 4 * lane);
                    rf.x += w * v.x; rf.y += w * v.y;
                    rf.z += w * v.z; rf.w += w * v.w;
                }
                __syncthreads();
            }
        }
        __syncthreads();  // protect sm/ssv reuse across directions
    }

    // head-mean via smem transpose
    *(float4*)&sred[wid][4 * lane] = rf;
    __syncthreads();
    float v = 0.25f * (sred[0][tid] + sred[1][tid] + sred[2][tid] + sred[3][tid]);
    size_t oi = (size_t)n * HID + tid;
    if (doResid) v += xout[oi];
    xout[oi] = v;
}

// ------------------- elementwise glue -------------------
__global__ void k_idcombine(const float* __restrict__ feat, float* __restrict__ h256) {
    int i = blockIdx.x * blockDim.x + threadIdx.x;
    if (i < NN * FDIM) {
        float f = feat[i];
        float h = h256[i];
        h256[i] = f + h * (1.f / (1.f + expf(-f)));
    }
}

// ------------------- batch norm -------------------
__global__ void k_bnstats(const float* __restrict__ h, float* __restrict__ bsum,
                          float* __restrict__ bsq) {
    __shared__ float s1[256], s2[256];
    int tid = threadIdx.x;
    int c = tid & 127;
    int half = tid >> 7;
    int rbeg = blockIdx.x * 128;
    int rend = rbeg + 128;
    if (rend > NN) rend = NN;
    float sm = 0.f, sq = 0.f;
    for (int r = rbeg + half; r < rend; r += 2) {
        float v = h[(size_t)r * HID + c];
        sm += v;
        sq += v * v;
    }
    s1[tid] = sm;
    s2[tid] = sq;
    __syncthreads();
    if (tid < 128) {
        atomicAdd(&bsum[c], s1[tid] + s1[tid + 128]);
        atomicAdd(&bsq[c], s2[tid] + s2[tid + 128]);
    }
}

__global__ void k_bnapply(const float* __restrict__ h, const float* __restrict__ bsum,
                          const float* __restrict__ bsq, const float* __restrict__ gamma,
                          const float* __restrict__ beta, float* __restrict__ out) {
    int i = blockIdx.x * blockDim.x + threadIdx.x;
    if (i < NN * HID) {
        int c = i & 127;
        float mu = bsum[c] * (1.f / NN);
        float var = bsq[c] * (1.f / NN) - mu * mu;
        out[i] = gamma[c] * (h[i] - mu) * rsqrtf(var + EPSB) + beta[c];
    }
}

// ------------------- launch -------------------
extern "C" void kernel_launch(void* const* d_in, const int* in_sizes, int n_in,
                              void* d_out, int out_size) {
    const float* feature  = (const float*)d_in[0];
    const float* ew_f     = (const float*)d_in[1];
    const float* ew_b     = (const float*)d_in[2];
    const float* W_id     = (const float*)d_in[3];
    const float* b_id     = (const float*)d_in[4];
    const float* W_gcnf   = (const float*)d_in[5];
    const float* b_gcnf   = (const float*)d_in[6];
    const float* W_gcnb   = (const float*)d_in[7];
    const float* b_gcnb   = (const float*)d_in[8];
    const float* W1       = (const float*)d_in[9];
    const float* b1       = (const float*)d_in[10];
    const float* gat_W    = (const float*)d_in[11];
    const float* gat_al   = (const float*)d_in[12];
    const float* gat_ar   = (const float*)d_in[13];
    const float* bn_gamma = (const float*)d_in[14];
    const float* bn_beta  = (const float*)d_in[15];
    const int*   src      = (const int*)d_in[16];
    const int*   dst      = (const int*)d_in[17];
    float* out = (float*)d_out;

    float *p_h256, *p_agg, *p_hidden, *p_x, *p_fsf, *p_fsb;
    float *p_elf, *p_erf, *p_elb, *p_erb, *p_bsum, *p_bsq;
    int *p_cin, *p_cout, *p_iin, *p_iout, *p_ein, *p_eout;
    cudaGetSymbolAddress((void**)&p_h256, g_h256);
    cudaGetSymbolAddress((void**)&p_agg, g_agg);
    cudaGetSymbolAddress((void**)&p_hidden, g_hidden);
    cudaGetSymbolAddress((void**)&p_x, g_x);
    cudaGetSymbolAddress((void**)&p_fsf, g_fsf);
    cudaGetSymbolAddress((void**)&p_fsb, g_fsb);
    cudaGetSymbolAddress((void**)&p_elf, g_elf);
    cudaGetSymbolAddress((void**)&p_erf, g_erf);
    cudaGetSymbolAddress((void**)&p_elb, g_elb);
    cudaGetSymbolAddress((void**)&p_erb, g_erb);
    cudaGetSymbolAddress((void**)&p_bsum, g_bsum);
    cudaGetSymbolAddress((void**)&p_bsq, g_bsq);
    cudaGetSymbolAddress((void**)&p_cin, g_cin);
    cudaGetSymbolAddress((void**)&p_cout, g_cout);
    cudaGetSymbolAddress((void**)&p_iin, g_iin);
    cudaGetSymbolAddress((void**)&p_iout, g_iout);
    cudaGetSymbolAddress((void**)&p_ein, g_ein);
    cudaGetSymbolAddress((void**)&p_eout, g_eout);

    const int EB = (NE + 255) / 256;
    const int NB = (NN + 255) / 256;
    const int NHB = (NN * HID + 255) / 256;
    const int NFB = (NN * FDIM + 255) / 256;
    const int WARPB = (NN * 32 + 127) / 128;
    const int MB = (NN + BM - 1) / BM;

    // --- CSR build (both directions, compacted) ---
    k_zero2<<<NB, 256>>>(p_cin, p_cout, NN);
    k_hist<<<EB, 256>>>(src, dst, p_cin, p_cout);
    k_scan2<<<2, 1024>>>(p_cin, p_iin, p_cout, p_iout);
    k_zero2<<<NB, 256>>>(p_cin, p_cout, NN);
    k_scatter2<<<2 * EB, 256>>>(dst, p_iin, p_cin, p_ein, src, p_iout, p_cout, p_eout);

    // --- Identity layer: lin + fwd WGCN + bwd WGCN ---
    {
        dim3 g(FDIM / BN, MB);
        k_gemm<<<g, 256>>>(feature, W_id, b_id, p_h256, NN, FDIM, FDIM, 0, 0,
                           (const float*)0, (float*)0, FDIM / BN);
        // both WGCN aggregations in one launch (bwd output reuses g_fsf)
        dim3 gw((NN + 3) / 4, 2);
        k_wgcn2<<<gw, 256>>>((const float4*)feature, ew_f, ew_b,
                             p_iin, p_ein, src, p_iout, p_eout, dst,
                             (float4*)p_agg, (float4*)p_fsf);
        k_gemm<<<g, 256>>>(p_agg, W_gcnf, b_gcnf, p_h256, NN, FDIM, FDIM, 1, 1,
                           (const float*)0, (float*)0, FDIM / BN);
        k_gemm<<<g, 256>>>(p_fsf, W_gcnb, b_gcnb, p_h256, NN, FDIM, FDIM, 1, 1,
                           (const float*)0, (float*)0, FDIM / BN);
        k_idcombine<<<NFB, 256>>>(feature, p_h256);
        dim3 g1(HID / BN, MB);
        k_gemm<<<g1, 256>>>(p_h256, W1, b1, p_hidden, NN, HID, FDIM, 0, 0,
                            (const float*)0, (float*)0, HID / BN);
    }

    // --- 2 layers x 2 GAT blocks ---
    for (int l = 0; l < 2; l++) {
        const float* xin = p_hidden;
        for (int blk = 0; blk < 2; blk++) {
            int base = (l * 2 + blk) * 2;
            const float* Wf = gat_W + (size_t)(base + 0) * HID * FSD;
            const float* Wb = gat_W + (size_t)(base + 1) * HID * FSD;
            const float* alf = gat_al + (size_t)(base + 0) * HEADS * DH;
            const float* arf = gat_ar + (size_t)(base + 0) * HEADS * DH;
            const float* alb = gat_al + (size_t)(base + 1) * HEADS * DH;
            const float* arb = gat_ar + (size_t)(base + 1) * HEADS * DH;

            dim3 g((FSD / BN) * 2, MB);
            k_gemm<<<g, 256>>>(xin, Wf, (const float*)0, p_fsf, NN, FSD, HID, 0, 0,
                               Wb, p_fsb, FSD / BN);
            k_elr2<<<WARPB, 128>>>(p_fsf, alf, arf, p_fsb, alb, arb,
                                   p_elf, p_erf, p_elb, p_erb);
            if (blk == 0) {
                k_gatblock<<<NN, 128>>>(p_fsf, p_fsb, p_elf, p_erf, p_elb, p_erb,
                                        p_iin, p_ein, src, p_iout, p_eout, dst,
                                        p_x, 0);
                xin = p_x;
            } else {
                k_gatblock<<<NN, 128>>>(p_fsf, p_fsb, p_elf, p_erf, p_elb, p_erb,
                                        p_iin, p_ein, src, p_iout, p_eout, dst,
                                        p_hidden, 1);
            }
        }
    }

    // --- BatchNorm ---
    k_zerof<<<1, 128>>>(p_bsum, HID);
    k_zerof<<<1, 128>>>(p_bsq, HID);
    k_bnstats<<<(NN + 127) / 128, 256>>>(p_hidden, p_bsum, p_bsq);
    k_bnapply<<<NHB, 256>>>(p_hidden, p_bsum, p_bsq, bn_gamma, bn_beta, out);
}